// round 8
// baseline (speedup 1.0000x reference)
#include <cuda_runtime.h>
#include <cuda_bf16.h>
#include <cstdint>

#define N_NODES 20000
#define N_EDGES 640000
#define K2_BLOCKS 444
#define K2_SMEM 74240

// ---------------- scratch (static device memory, no allocation) ----------------
__device__ float g_y0 [N_NODES * 32];
__device__ float g_y1t[N_NODES * 3 * 32];
__device__ float g_y2t[N_NODES * 5 * 32];
__device__ float g_sc [3 * N_NODES * 32];
__device__ float g_mid[N_NODES * 96];
__device__ int   g_hist[N_NODES];
__device__ int   g_cnt [N_NODES];
__device__ int   g_basep[N_NODES];
__device__ int   g_perm[N_EDGES];

__device__ __forceinline__ float silu_f(float x) {
    return __fdividef(x, 1.0f + __expf(-x));
}
__device__ __forceinline__ unsigned long long fma2(unsigned long long a,
                                                   unsigned long long b,
                                                   unsigned long long c) {
    unsigned long long d;
    asm("fma.rn.f32x2 %0, %1, %2, %3;" : "=l"(d) : "l"(a), "l"(b), "l"(c));
    return d;
}
__device__ __forceinline__ unsigned long long pack2(float lo, float hi) {
    unsigned long long p;
    asm("mov.b64 %0, {%1, %2};" : "=l"(p) : "f"(lo), "f"(hi));
    return p;
}
__device__ __forceinline__ uint32_t smem_u32(const void* p) {
    uint32_t a;
    asm("{ .reg .u64 t; cvta.to.shared.u64 t, %1; cvt.u32.u64 %0, t; }" : "=r"(a) : "l"(p));
    return a;
}

// ---------------- sort kernels: counting sort of edges by destination ----------------
__global__ void k0a_zero() {
    int i = blockIdx.x * blockDim.x + threadIdx.x;
    if (i < N_NODES) { g_hist[i] = 0; g_cnt[i] = 0; }
}
__global__ void k0b_hist(const int* __restrict__ eidx) {
    int e = blockIdx.x * blockDim.x + threadIdx.x;
    if (e < N_EDGES) atomicAdd(&g_hist[__ldg(eidx + N_EDGES + e)], 1);
}
__global__ void k0c_scan() {
    __shared__ int sm[1024];
    int t = threadIdx.x;
    int start = t * 20;
    int loc[20];
    int tot = 0;
#pragma unroll
    for (int j = 0; j < 20; j++) {
        int b = start + j;
        loc[j] = tot;
        if (b < N_NODES) tot += g_hist[b];
    }
    sm[t] = tot;
    __syncthreads();
    for (int off = 1; off < 1024; off <<= 1) {
        int v = (t >= off) ? sm[t - off] : 0;
        __syncthreads();
        sm[t] += v;
        __syncthreads();
    }
    int base = sm[t] - tot;
#pragma unroll
    for (int j = 0; j < 20; j++) {
        int b = start + j;
        if (b < N_NODES) g_basep[b] = base + loc[j];
    }
}
__global__ void k0d_place(const int* __restrict__ eidx) {
    int e = blockIdx.x * blockDim.x + threadIdx.x;
    if (e < N_EDGES) {
        int d = __ldg(eidx + N_EDGES + e);
        int pos = g_basep[d] + atomicAdd(&g_cnt[d], 1);
        g_perm[pos] = e;
    }
}

// ---------------- Kernel 1 (merged): k1a pre-linear (+zero mid) | k1b self-connection ----------------
__global__ void k1_kernel(const float* __restrict__ x,
                          const float* __restrict__ na,
                          const float* __restrict__ W1_0,
                          const float* __restrict__ W1_1,
                          const float* __restrict__ W1_2,
                          const float* __restrict__ scW)
{
    extern __shared__ __align__(16) float dsm[];
    int t = threadIdx.x;

    if (blockIdx.x < 2500) {
        float* w0s = dsm;
        float* w1s = dsm + 1024;
        float* w2s = dsm + 2048;
        for (int i = t; i < 1024; i += blockDim.x) {
            w0s[i] = W1_0[i]; w1s[i] = W1_1[i]; w2s[i] = W1_2[i];
        }
        __syncthreads();

        int lane = t & 31;
        int n = (int)((blockIdx.x * blockDim.x + t) >> 5);
        if (n >= N_NODES) return;

        const float* xr = x + (size_t)n * 288;
        float x0r = xr[lane];
        float x1r[3], x2r[5];
#pragma unroll
        for (int m = 0; m < 3; m++) x1r[m] = xr[32 + lane * 3 + m];
#pragma unroll
        for (int m = 0; m < 5; m++) x2r[m] = xr[128 + lane * 5 + m];

        float a0 = 0.f;
        float a1[3] = {0.f, 0.f, 0.f};
        float a2[5] = {0.f, 0.f, 0.f, 0.f, 0.f};
#pragma unroll
        for (int u = 0; u < 32; u++) {
            float xv0 = __shfl_sync(0xffffffffu, x0r, u);
            a0 = fmaf(xv0, w0s[u * 32 + lane], a0);
#pragma unroll
            for (int m = 0; m < 3; m++) {
                float xv = __shfl_sync(0xffffffffu, x1r[m], u);
                a1[m] = fmaf(xv, w1s[u * 32 + lane], a1[m]);
            }
#pragma unroll
            for (int m = 0; m < 5; m++) {
                float xv = __shfl_sync(0xffffffffu, x2r[m], u);
                a2[m] = fmaf(xv, w2s[u * 32 + lane], a2[m]);
            }
        }
        const float inv = 0.17677669529663687f;
        g_y0[n * 32 + lane] = a0 * inv;
#pragma unroll
        for (int m = 0; m < 3; m++) g_y1t[(n * 3 + m) * 32 + lane] = a1[m] * inv;
#pragma unroll
        for (int m = 0; m < 5; m++) g_y2t[(n * 5 + m) * 32 + lane] = a2[m] * inv;

        g_mid[n * 96 + lane]      = 0.f;
        g_mid[n * 96 + 32 + lane] = 0.f;
        g_mid[n * 96 + 64 + lane] = 0.f;
    } else {
        float* s = dsm;
        for (int i = t; i < 12288; i += blockDim.x) s[i] = scW[i];
        __syncthreads();

        int lane = t & 31;
        int n = (int)(((blockIdx.x - 2500) * blockDim.x + t) >> 5);
        if (n >= N_NODES) return;

        float x0r = x[(size_t)n * 288 + lane];
        float nar = (lane < 4) ? na[n * 4 + lane] : 0.f;
        float na0 = __shfl_sync(0xffffffffu, nar, 0);
        float na1 = __shfl_sync(0xffffffffu, nar, 1);
        float na2 = __shfl_sync(0xffffffffu, nar, 2);
        float na3 = __shfl_sync(0xffffffffu, nar, 3);

        float acc[3] = {0.f, 0.f, 0.f};
#pragma unroll
        for (int u = 0; u < 32; u++) {
            float x0u = __shfl_sync(0xffffffffu, x0r, u);
            float c0 = x0u * na0, c1 = x0u * na1, c2 = x0u * na2, c3 = x0u * na3;
#pragma unroll
            for (int h = 0; h < 3; h++) {
                const float* p = s + ((h * 32 + u) * 4) * 32 + lane;
                acc[h] = fmaf(c0, p[0],  acc[h]);
                acc[h] = fmaf(c1, p[32], acc[h]);
                acc[h] = fmaf(c2, p[64], acc[h]);
                acc[h] = fmaf(c3, p[96], acc[h]);
            }
        }
        const float invs = 0.08838834764831845f;
#pragma unroll
        for (int h = 0; h < 3; h++)
            g_sc[h * (N_NODES * 32) + n * 32 + lane] = acc[h] * invs;
    }
}

// ---------------- Kernel 2: HMMA edge pipeline over destination-sorted edges ----------------
// 128 threads = 4 independent warps; each warp owns 16 sorted-edge slots per iteration.
// smem: wm0s f32[512] | W bf16[96][136] | H bf16[4][16][136] | zbuf f32[4][16][100] |
//       ea f32[4][144] | pbuf int[4][48] (pe/ps/pd)
__global__ void __launch_bounds__(128, 3) k2_kernel(const float* __restrict__ ee,
                          const float* __restrict__ ea,
                          const int*   __restrict__ eidx,
                          const float* __restrict__ Wm0,
                          const float* __restrict__ Wm1)
{
    extern __shared__ __align__(16) unsigned char smraw[];
    float*          wm0s = (float*)smraw;                          // [0, 2048)
    __nv_bfloat16*  Wb   = (__nv_bfloat16*)(smraw + 2048);         // [2048, 28160)
    float*          zbuf = (float*)(smraw + 45568);                // [45568, 71168)
    float*          ea_s = (float*)(smraw + 71168);                // [71168, 73472)
    int*            pbuf = (int*)  (smraw + 73472);                // [73472, 74240)

    const uint32_t sb    = smem_u32(smraw);
    const uint32_t W_u32 = sb + 2048;
    const uint32_t H_u32 = sb + 28160;

    int tid  = threadIdx.x;
    int lane = tid & 31;
    int wrp  = tid >> 5;

    const float inv8 = 0.35355339059327373f;
    const float C0 = 0.125f * 0.17677669529663687f;
    const float C1 = C0 * 0.5773502691896258f;
    const float C2 = C0 * 0.4472135954999579f;

    for (int i = tid; i < 512; i += 128) wm0s[i] = Wm0[i] * inv8;
    for (int i = tid; i < 96 * 64; i += 128) {
        int n = i >> 6, k = i & 63;
        float Cn = (n < 32) ? C0 : (n < 64) ? C1 : C2;
        float w = Wm1[k * 96 + n] * Cn;
        __nv_bfloat16 hb = __float2bfloat16(w);
        Wb[n * 136 + k]      = hb;
        Wb[n * 136 + 64 + k] = __float2bfloat16(w - __bfloat162float(hb));
    }
    __syncthreads();

    float* ea_w = ea_s + wrp * 144;
    float* zb   = zbuf + wrp * 1600;
    int*   pe_w = pbuf + wrp * 48;
    int*   ps_w = pe_w + 16;
    int*   pd_w = pe_w + 32;
    const uint32_t Hw = H_u32 + wrp * 4352;

    int eloc = lane >> 1, half = lane & 1;
    const float* wp = wm0s + (half << 5);

    const uint32_t a_base = Hw + (uint32_t)(lane & 15) * 272 + (uint32_t)((lane >> 4) & 1) * 16;
    const uint32_t b_base = W_u32 + (uint32_t)(lane & 7) * 272 + (uint32_t)((lane >> 3) & 1) * 16;
    const uint32_t hrow = Hw + (uint32_t)eloc * 272 + (uint32_t)half * 64;

    int wg = blockIdx.x * 4 + wrp;
    int nw = gridDim.x * 4;

    for (int g = wg; g < N_EDGES / 16; g += nw) {
        int base = g * 16;

        // ---- load permuted edge ids + src/dst into per-warp smem ----
        if (lane < 16) {
            int pv = __ldg(&g_perm[base + lane]);
            pe_w[lane] = pv;
            ps_w[lane] = __ldg(eidx + pv);
            pd_w[lane] = __ldg(eidx + N_EDGES + pv);
        }
        __syncwarp();

        // ---- stage edge attrs (gathered via perm) ----
        for (int i = lane; i < 144; i += 32) {
            int le = i / 9, c = i - le * 9;
            ea_w[i] = __ldg(ea + (size_t)pe_w[le] * 9 + c);
        }

        // ---- first MLP: 2 lanes per edge ----
        float ev[8];
        {
            const float4* p = (const float4*)(ee + (size_t)pe_w[eloc] * 8);
            float4 va = __ldg(p), vb = __ldg(p + 1);
            ev[0]=va.x; ev[1]=va.y; ev[2]=va.z; ev[3]=va.w;
            ev[4]=vb.x; ev[5]=vb.y; ev[6]=vb.z; ev[7]=vb.w;
        }
        unsigned long long hacc[16];
#pragma unroll
        for (int j = 0; j < 16; j++) hacc[j] = 0ull;
#pragma unroll
        for (int k = 0; k < 8; k++) {
            unsigned long long ek2 = pack2(ev[k], ev[k]);
            const ulonglong2* q = (const ulonglong2*)(wp + (k << 6));
#pragma unroll
            for (int j = 0; j < 8; j++) {
                ulonglong2 v = q[j];
                hacc[2 * j]     = fma2(ek2, v.x, hacc[2 * j]);
                hacc[2 * j + 1] = fma2(ek2, v.y, hacc[2 * j + 1]);
            }
        }
#pragma unroll
        for (int j = 0; j < 16; j++) {
            float s0, s1;
            asm("mov.b64 {%0,%1}, %2;" : "=f"(s0), "=f"(s1) : "l"(hacc[j]));
            s0 = silu_f(s0); s1 = silu_f(s1);
            uint32_t hb;
            asm("cvt.rn.bf16x2.f32 %0, %1, %2;" : "=r"(hb) : "f"(s1), "f"(s0));
            float f0 = __uint_as_float(hb << 16);
            float f1 = __uint_as_float(hb & 0xFFFF0000u);
            float r0 = s0 - f0, r1 = s1 - f1;
            uint32_t lb;
            asm("cvt.rn.bf16x2.f32 %0, %1, %2;" : "=r"(lb) : "f"(r1), "f"(r0));
            asm volatile("st.shared.b32 [%0], %1;" :: "r"(hrow + j * 4), "r"(hb) : "memory");
            asm volatile("st.shared.b32 [%0], %1;" :: "r"(hrow + 128 + j * 4), "r"(lb) : "memory");
        }
        __syncwarp();

        // ---- hoisted gather contraction -> zbuf ----
#pragma unroll
        for (int le = 0; le < 16; le++) {
            int s = ps_w[le];
            const float* eap = ea_w + le * 9;
            float y0v = __ldg(g_y0 + (size_t)s * 32 + lane);
            float z1 = __ldg(g_y1t + (size_t)s * 96 + lane) * eap[1];
            z1 = fmaf(__ldg(g_y1t + (size_t)s * 96 + 32 + lane), eap[2], z1);
            z1 = fmaf(__ldg(g_y1t + (size_t)s * 96 + 64 + lane), eap[3], z1);
            float z2 = __ldg(g_y2t + (size_t)s * 160 + lane) * eap[4];
            z2 = fmaf(__ldg(g_y2t + (size_t)s * 160 + 32 + lane),  eap[5], z2);
            z2 = fmaf(__ldg(g_y2t + (size_t)s * 160 + 64 + lane),  eap[6], z2);
            z2 = fmaf(__ldg(g_y2t + (size_t)s * 160 + 96 + lane),  eap[7], z2);
            z2 = fmaf(__ldg(g_y2t + (size_t)s * 160 + 128 + lane), eap[8], z2);

            zb[le * 100 + lane]      = y0v * eap[0];
            zb[le * 100 + 32 + lane] = z1;
            zb[le * 100 + 64 + lane] = z2;
        }
        __syncwarp();

        // ---- GEMM: D[16,96] = Hhi*Whi + Hlo*Whi + Hhi*Wlo ----
        float acc[48];
#pragma unroll
        for (int i = 0; i < 48; i++) acc[i] = 0.f;
#pragma unroll
        for (int k = 0; k < 4; k++) {
            uint32_t ah0, ah1, ah2, ah3, al0, al1, al2, al3;
            asm volatile("ldmatrix.sync.aligned.m8n8.x4.shared.b16 {%0,%1,%2,%3}, [%4];"
                         : "=r"(ah0), "=r"(ah1), "=r"(ah2), "=r"(ah3)
                         : "r"(a_base + k * 32));
            asm volatile("ldmatrix.sync.aligned.m8n8.x4.shared.b16 {%0,%1,%2,%3}, [%4];"
                         : "=r"(al0), "=r"(al1), "=r"(al2), "=r"(al3)
                         : "r"(a_base + 128 + k * 32));
#pragma unroll
            for (int n = 0; n < 12; n++) {
                uint32_t baddr = b_base + (uint32_t)n * 2176 + k * 32;
                uint32_t bh0, bh1, bl0, bl1;
                asm volatile("ldmatrix.sync.aligned.m8n8.x2.shared.b16 {%0,%1}, [%2];"
                             : "=r"(bh0), "=r"(bh1) : "r"(baddr));
                asm volatile("ldmatrix.sync.aligned.m8n8.x2.shared.b16 {%0,%1}, [%2];"
                             : "=r"(bl0), "=r"(bl1) : "r"(baddr + 128));
                float* d = acc + n * 4;
                asm volatile("mma.sync.aligned.m16n8k16.row.col.f32.bf16.bf16.f32 "
                             "{%0,%1,%2,%3}, {%4,%5,%6,%7}, {%8,%9}, {%0,%1,%2,%3};"
                             : "+f"(d[0]), "+f"(d[1]), "+f"(d[2]), "+f"(d[3])
                             : "r"(ah0), "r"(ah1), "r"(ah2), "r"(ah3), "r"(bh0), "r"(bh1));
                asm volatile("mma.sync.aligned.m16n8k16.row.col.f32.bf16.bf16.f32 "
                             "{%0,%1,%2,%3}, {%4,%5,%6,%7}, {%8,%9}, {%0,%1,%2,%3};"
                             : "+f"(d[0]), "+f"(d[1]), "+f"(d[2]), "+f"(d[3])
                             : "r"(al0), "r"(al1), "r"(al2), "r"(al3), "r"(bh0), "r"(bh1));
                asm volatile("mma.sync.aligned.m16n8k16.row.col.f32.bf16.bf16.f32 "
                             "{%0,%1,%2,%3}, {%4,%5,%6,%7}, {%8,%9}, {%0,%1,%2,%3};"
                             : "+f"(d[0]), "+f"(d[1]), "+f"(d[2]), "+f"(d[3])
                             : "r"(ah0), "r"(ah1), "r"(ah2), "r"(ah3), "r"(bl0), "r"(bl1));
            }
        }

        // ---- fused epilogue: multiply D fragment by zbuf in place ----
        {
            int q = lane >> 2, tg = lane & 3;
#pragma unroll
            for (int n = 0; n < 12; n++) {
                int col = n * 8 + tg * 2;
                float2 za = *(float2*)&zb[q * 100 + col];
                float2 zc = *(float2*)&zb[(q + 8) * 100 + col];
                za.x *= acc[n * 4];     za.y *= acc[n * 4 + 1];
                zc.x *= acc[n * 4 + 2]; zc.y *= acc[n * 4 + 3];
                *(float2*)&zb[q * 100 + col]       = za;
                *(float2*)&zb[(q + 8) * 100 + col] = zc;
            }
        }
        __syncwarp();

        // ---- segmented scatter: accumulate runs of equal destination ----
        if (lane < 24) {
            float4 a4 = *(const float4*)&zb[lane * 4];
            int dprev = pd_w[0];
#pragma unroll
            for (int le = 1; le < 16; le++) {
                float4 v = *(const float4*)&zb[le * 100 + lane * 4];
                int dcur = pd_w[le];
                if (dcur == dprev) {
                    a4.x += v.x; a4.y += v.y; a4.z += v.z; a4.w += v.w;
                } else {
                    float* p = &g_mid[(size_t)dprev * 96 + lane * 4];
                    asm volatile("red.global.add.v4.f32 [%0], {%1,%2,%3,%4};"
                                 :: "l"(p), "f"(a4.x), "f"(a4.y), "f"(a4.z), "f"(a4.w)
                                 : "memory");
                    a4 = v; dprev = dcur;
                }
            }
            float* p = &g_mid[(size_t)dprev * 96 + lane * 4];
            asm volatile("red.global.add.v4.f32 [%0], {%1,%2,%3,%4};"
                         :: "l"(p), "f"(a4.x), "f"(a4.y), "f"(a4.z), "f"(a4.w)
                         : "memory");
        }
        __syncwarp();
    }
}

// ---------------- Kernel 3: node finalize ----------------
__global__ void k3_kernel(const float* __restrict__ l2_0,
                          const float* __restrict__ l2_1,
                          const float* __restrict__ l2_2,
                          float* __restrict__ out)
{
    __shared__ __align__(16) float s0t[32 * 36];
    __shared__ __align__(16) float s1t[32 * 68];
    __shared__ __align__(16) float s2t[32 * 100];
    __shared__ __align__(16) float mb[8][96];

    int t = threadIdx.x;
    for (int i = t; i < 1024; i += blockDim.x) { int k = i / 32, w = i % 32; s0t[w * 36 + k]  = l2_0[i]; }
    for (int i = t; i < 2048; i += blockDim.x) { int k = i / 32, w = i % 32; s1t[w * 68 + k]  = l2_1[i]; }
    for (int i = t; i < 3072; i += blockDim.x) { int k = i / 32, w = i % 32; s2t[w * 100 + k] = l2_2[i]; }
    __syncthreads();

    int lane = t & 31;
    int wrp  = t >> 5;
    int n = (int)((blockIdx.x * blockDim.x + t) >> 5);
    if (n >= N_NODES) return;

    mb[wrp][lane]      = g_mid[n * 96 + lane];
    mb[wrp][32 + lane] = g_mid[n * 96 + 32 + lane];
    mb[wrp][64 + lane] = g_mid[n * 96 + 64 + lane];
    __syncwarp();

    unsigned long long A0 = 0ull, A1 = 0ull, A2 = 0ull, B2 = 0ull;
    const float* p0 = &s0t[lane * 36];
    const float* p1 = &s1t[lane * 68];
    const float* p2 = &s2t[lane * 100];
#pragma unroll
    for (int c = 0; c < 24; c++) {
        int k = c * 4;
        ulonglong2 m4 = *(const ulonglong2*)&mb[wrp][k];
        ulonglong2 q2 = *(const ulonglong2*)(p2 + k);
        A2 = fma2(m4.x, q2.x, A2);
        B2 = fma2(m4.y, q2.y, B2);
        if (c < 16) {
            ulonglong2 q1 = *(const ulonglong2*)(p1 + k);
            A1 = fma2(m4.x, q1.x, A1);
            A1 = fma2(m4.y, q1.y, A1);
        }
        if (c < 8) {
            ulonglong2 q0 = *(const ulonglong2*)(p0 + k);
            A0 = fma2(m4.x, q0.x, A0);
            A0 = fma2(m4.y, q0.y, A0);
        }
    }

    const float i32 = 0.17677669529663687f;
    const float i64 = 0.125f;
    const float i96 = 0.10206207261596575f;

    float a0lo, a0hi, a1lo, a1hi, a2lo, a2hi, b2lo, b2hi;
    asm("mov.b64 {%0,%1}, %2;" : "=f"(a0lo), "=f"(a0hi) : "l"(A0));
    asm("mov.b64 {%0,%1}, %2;" : "=f"(a1lo), "=f"(a1hi) : "l"(A1));
    asm("mov.b64 {%0,%1}, %2;" : "=f"(a2lo), "=f"(a2hi) : "l"(A2));
    asm("mov.b64 {%0,%1}, %2;" : "=f"(b2lo), "=f"(b2hi) : "l"(B2));

    float o0 = silu_f(fmaf(a0lo + a0hi, i32, g_sc[                   n * 32 + lane]));
    float o1 = silu_f(fmaf(a1lo + a1hi, i64, g_sc[N_NODES * 32     + n * 32 + lane]));
    float o2 = silu_f(fmaf((a2lo + a2hi) + (b2lo + b2hi), i96, g_sc[2 * N_NODES * 32 + n * 32 + lane]));

    out[                   n * 32 + lane] = o0;
    out[N_NODES * 32     + n * 32 + lane] = o1;
    out[2 * N_NODES * 32  + n * 32 + lane] = o2;
}

// ---------------- launch ----------------
extern "C" void kernel_launch(void* const* d_in, const int* in_sizes, int n_in,
                              void* d_out, int out_size)
{
    const float* x      = (const float*)d_in[0];
    const float* na     = (const float*)d_in[1];
    const float* ee     = (const float*)d_in[2];
    const float* ea     = (const float*)d_in[3];
    const int*   eidx   = (const int*)  d_in[4];
    const float* W1_0   = (const float*)d_in[5];
    const float* W1_1   = (const float*)d_in[6];
    const float* W1_2   = (const float*)d_in[7];
    const float* Wm0    = (const float*)d_in[8];
    const float* Wm1    = (const float*)d_in[9];
    const float* l2_0   = (const float*)d_in[10];
    const float* l2_1   = (const float*)d_in[11];
    const float* l2_2   = (const float*)d_in[12];
    const float* scW    = (const float*)d_in[13];
    float* out = (float*)d_out;

    cudaFuncSetAttribute(k1_kernel, cudaFuncAttributeMaxDynamicSharedMemorySize, 49152);
    cudaFuncSetAttribute(k2_kernel, cudaFuncAttributeMaxDynamicSharedMemorySize, K2_SMEM);

    k0a_zero <<<(N_NODES + 255) / 256, 256>>>();
    k0b_hist <<<(N_EDGES + 255) / 256, 256>>>(eidx);
    k0c_scan <<<1, 1024>>>();
    k0d_place<<<(N_EDGES + 255) / 256, 256>>>(eidx);
    k1_kernel<<<5000, 256, 49152>>>(x, na, W1_0, W1_1, W1_2, scW);
    k2_kernel<<<K2_BLOCKS, 128, K2_SMEM>>>(ee, ea, eidx, Wm0, Wm1);
    k3_kernel<<<2500, 256>>>(l2_0, l2_1, l2_2, out);
    (void)in_sizes; (void)n_in; (void)out_size;
}

// round 9
// speedup vs baseline: 1.1188x; 1.1188x over previous
#include <cuda_runtime.h>
#include <cuda_bf16.h>
#include <cstdint>

#define N_NODES 20000
#define N_EDGES 640000
#define K2_BLOCKS 444
#define K2_SMEM 74240

// ---------------- scratch (static device memory, no allocation) ----------------
__device__ float g_y0 [N_NODES * 32];
__device__ float g_y1t[N_NODES * 3 * 32];
__device__ float g_y2t[N_NODES * 5 * 32];
__device__ float g_sc [3 * N_NODES * 32];
__device__ float g_mid[N_NODES * 96];
__device__ int   g_hist[N_NODES];
__device__ int   g_cnt [N_NODES];
__device__ int   g_basep[N_NODES];
__device__ int   g_perm [N_EDGES];
__device__ int   g_srt_s[N_EDGES];
__device__ int   g_srt_d[N_EDGES];

__device__ __forceinline__ float silu_f(float x) {
    return __fdividef(x, 1.0f + __expf(-x));
}
__device__ __forceinline__ unsigned long long fma2(unsigned long long a,
                                                   unsigned long long b,
                                                   unsigned long long c) {
    unsigned long long d;
    asm("fma.rn.f32x2 %0, %1, %2, %3;" : "=l"(d) : "l"(a), "l"(b), "l"(c));
    return d;
}
__device__ __forceinline__ unsigned long long pack2(float lo, float hi) {
    unsigned long long p;
    asm("mov.b64 %0, {%1, %2};" : "=l"(p) : "f"(lo), "f"(hi));
    return p;
}
__device__ __forceinline__ uint32_t smem_u32(const void* p) {
    uint32_t a;
    asm("{ .reg .u64 t; cvta.to.shared.u64 t, %1; cvt.u32.u64 %0, t; }" : "=r"(a) : "l"(p));
    return a;
}

// ---------------- sort kernels: counting sort of edges by SOURCE ----------------
__global__ void k0a_zero() {
    int i = blockIdx.x * blockDim.x + threadIdx.x;
    if (i < N_NODES) { g_hist[i] = 0; g_cnt[i] = 0; }
}
__global__ void k0b_hist(const int* __restrict__ eidx) {
    int e = blockIdx.x * blockDim.x + threadIdx.x;
    if (e < N_EDGES) atomicAdd(&g_hist[__ldg(eidx + e)], 1);
}
__global__ void k0c_scan() {
    __shared__ int sm[1024];
    int t = threadIdx.x;
    int start = t * 20;
    int loc[20];
    int tot = 0;
#pragma unroll
    for (int j = 0; j < 20; j++) {
        int b = start + j;
        loc[j] = tot;
        if (b < N_NODES) tot += g_hist[b];
    }
    sm[t] = tot;
    __syncthreads();
    for (int off = 1; off < 1024; off <<= 1) {
        int v = (t >= off) ? sm[t - off] : 0;
        __syncthreads();
        sm[t] += v;
        __syncthreads();
    }
    int base = sm[t] - tot;
#pragma unroll
    for (int j = 0; j < 20; j++) {
        int b = start + j;
        if (b < N_NODES) g_basep[b] = base + loc[j];
    }
}
__global__ void k0d_place(const int* __restrict__ eidx) {
    int e = blockIdx.x * blockDim.x + threadIdx.x;
    if (e < N_EDGES) {
        int s = __ldg(eidx + e);
        int pos = g_basep[s] + atomicAdd(&g_cnt[s], 1);
        g_perm [pos] = e;
        g_srt_s[pos] = s;
        g_srt_d[pos] = __ldg(eidx + N_EDGES + e);
    }
}

// ---------------- Kernel 1 (merged): k1a pre-linear (+zero mid) | k1b self-connection ----------------
__global__ void k1_kernel(const float* __restrict__ x,
                          const float* __restrict__ na,
                          const float* __restrict__ W1_0,
                          const float* __restrict__ W1_1,
                          const float* __restrict__ W1_2,
                          const float* __restrict__ scW)
{
    extern __shared__ __align__(16) float dsm[];
    int t = threadIdx.x;

    if (blockIdx.x < 2500) {
        float* w0s = dsm;
        float* w1s = dsm + 1024;
        float* w2s = dsm + 2048;
        for (int i = t; i < 1024; i += blockDim.x) {
            w0s[i] = W1_0[i]; w1s[i] = W1_1[i]; w2s[i] = W1_2[i];
        }
        __syncthreads();

        int lane = t & 31;
        int n = (int)((blockIdx.x * blockDim.x + t) >> 5);
        if (n >= N_NODES) return;

        const float* xr = x + (size_t)n * 288;
        float x0r = xr[lane];
        float x1r[3], x2r[5];
#pragma unroll
        for (int m = 0; m < 3; m++) x1r[m] = xr[32 + lane * 3 + m];
#pragma unroll
        for (int m = 0; m < 5; m++) x2r[m] = xr[128 + lane * 5 + m];

        float a0 = 0.f;
        float a1[3] = {0.f, 0.f, 0.f};
        float a2[5] = {0.f, 0.f, 0.f, 0.f, 0.f};
#pragma unroll
        for (int u = 0; u < 32; u++) {
            float xv0 = __shfl_sync(0xffffffffu, x0r, u);
            a0 = fmaf(xv0, w0s[u * 32 + lane], a0);
#pragma unroll
            for (int m = 0; m < 3; m++) {
                float xv = __shfl_sync(0xffffffffu, x1r[m], u);
                a1[m] = fmaf(xv, w1s[u * 32 + lane], a1[m]);
            }
#pragma unroll
            for (int m = 0; m < 5; m++) {
                float xv = __shfl_sync(0xffffffffu, x2r[m], u);
                a2[m] = fmaf(xv, w2s[u * 32 + lane], a2[m]);
            }
        }
        const float inv = 0.17677669529663687f;
        g_y0[n * 32 + lane] = a0 * inv;
#pragma unroll
        for (int m = 0; m < 3; m++) g_y1t[(n * 3 + m) * 32 + lane] = a1[m] * inv;
#pragma unroll
        for (int m = 0; m < 5; m++) g_y2t[(n * 5 + m) * 32 + lane] = a2[m] * inv;

        g_mid[n * 96 + lane]      = 0.f;
        g_mid[n * 96 + 32 + lane] = 0.f;
        g_mid[n * 96 + 64 + lane] = 0.f;
    } else {
        float* s = dsm;
        for (int i = t; i < 12288; i += blockDim.x) s[i] = scW[i];
        __syncthreads();

        int lane = t & 31;
        int n = (int)(((blockIdx.x - 2500) * blockDim.x + t) >> 5);
        if (n >= N_NODES) return;

        float x0r = x[(size_t)n * 288 + lane];
        float nar = (lane < 4) ? na[n * 4 + lane] : 0.f;
        float na0 = __shfl_sync(0xffffffffu, nar, 0);
        float na1 = __shfl_sync(0xffffffffu, nar, 1);
        float na2 = __shfl_sync(0xffffffffu, nar, 2);
        float na3 = __shfl_sync(0xffffffffu, nar, 3);

        float acc[3] = {0.f, 0.f, 0.f};
#pragma unroll
        for (int u = 0; u < 32; u++) {
            float x0u = __shfl_sync(0xffffffffu, x0r, u);
            float c0 = x0u * na0, c1 = x0u * na1, c2 = x0u * na2, c3 = x0u * na3;
#pragma unroll
            for (int h = 0; h < 3; h++) {
                const float* p = s + ((h * 32 + u) * 4) * 32 + lane;
                acc[h] = fmaf(c0, p[0],  acc[h]);
                acc[h] = fmaf(c1, p[32], acc[h]);
                acc[h] = fmaf(c2, p[64], acc[h]);
                acc[h] = fmaf(c3, p[96], acc[h]);
            }
        }
        const float invs = 0.08838834764831845f;
#pragma unroll
        for (int h = 0; h < 3; h++)
            g_sc[h * (N_NODES * 32) + n * 32 + lane] = acc[h] * invs;
    }
}

// ---------------- Kernel 2: HMMA edge pipeline over SOURCE-sorted edges ----------------
// 128 threads = 4 independent warps; each warp owns 16 sorted-edge slots per iteration.
// Gather y[src] once per distinct source (run-detection; warp-uniform branch).
__global__ void __launch_bounds__(128, 3) k2_kernel(const float* __restrict__ ee,
                          const float* __restrict__ ea,
                          const int*   __restrict__ eidx,
                          const float* __restrict__ Wm0,
                          const float* __restrict__ Wm1)
{
    extern __shared__ __align__(16) unsigned char smraw[];
    float*          wm0s = (float*)smraw;                          // [0, 2048)
    __nv_bfloat16*  Wb   = (__nv_bfloat16*)(smraw + 2048);         // [2048, 28160)
    float*          zbuf = (float*)(smraw + 45568);                // [45568, 71168)
    float*          ea_s = (float*)(smraw + 71168);                // [71168, 73472)
    int*            pbuf = (int*)  (smraw + 73472);                // [73472, 74240)

    const uint32_t sb    = smem_u32(smraw);
    const uint32_t W_u32 = sb + 2048;
    const uint32_t H_u32 = sb + 28160;

    int tid  = threadIdx.x;
    int lane = tid & 31;
    int wrp  = tid >> 5;

    const float inv8 = 0.35355339059327373f;
    const float C0 = 0.125f * 0.17677669529663687f;
    const float C1 = C0 * 0.5773502691896258f;
    const float C2 = C0 * 0.4472135954999579f;

    for (int i = tid; i < 512; i += 128) wm0s[i] = Wm0[i] * inv8;
    for (int i = tid; i < 96 * 64; i += 128) {
        int n = i >> 6, k = i & 63;
        float Cn = (n < 32) ? C0 : (n < 64) ? C1 : C2;
        float w = Wm1[k * 96 + n] * Cn;
        __nv_bfloat16 hb = __float2bfloat16(w);
        Wb[n * 136 + k]      = hb;
        Wb[n * 136 + 64 + k] = __float2bfloat16(w - __bfloat162float(hb));
    }
    __syncthreads();

    float* ea_w = ea_s + wrp * 144;
    float* zb   = zbuf + wrp * 1600;
    int*   pe_w = pbuf + wrp * 48;
    int*   ps_w = pe_w + 16;
    int*   pd_w = pe_w + 32;
    const uint32_t Hw = H_u32 + wrp * 4352;

    int eloc = lane >> 1, half = lane & 1;
    const float* wp = wm0s + (half << 5);

    const uint32_t a_base = Hw + (uint32_t)(lane & 15) * 272 + (uint32_t)((lane >> 4) & 1) * 16;
    const uint32_t b_base = W_u32 + (uint32_t)(lane & 7) * 272 + (uint32_t)((lane >> 3) & 1) * 16;
    const uint32_t hrow = Hw + (uint32_t)eloc * 272 + (uint32_t)half * 64;

    int wg = blockIdx.x * 4 + wrp;
    int nw = gridDim.x * 4;

    for (int g = wg; g < N_EDGES / 16; g += nw) {
        int base = g * 16;

        // ---- load sorted edge ids + src/dst ----
        if (lane < 16) {
            pe_w[lane] = __ldg(&g_perm [base + lane]);
            ps_w[lane] = __ldg(&g_srt_s[base + lane]);
            pd_w[lane] = __ldg(&g_srt_d[base + lane]);
        }
        __syncwarp();

        // ---- stage edge attrs (gathered via perm) ----
        for (int i = lane; i < 144; i += 32) {
            int le = i / 9, c = i - le * 9;
            ea_w[i] = __ldg(ea + (size_t)pe_w[le] * 9 + c);
        }

        // ---- first MLP: 2 lanes per edge ----
        float ev[8];
        {
            const float4* p = (const float4*)(ee + (size_t)pe_w[eloc] * 8);
            float4 va = __ldg(p), vb = __ldg(p + 1);
            ev[0]=va.x; ev[1]=va.y; ev[2]=va.z; ev[3]=va.w;
            ev[4]=vb.x; ev[5]=vb.y; ev[6]=vb.z; ev[7]=vb.w;
        }
        unsigned long long hacc[16];
#pragma unroll
        for (int j = 0; j < 16; j++) hacc[j] = 0ull;
#pragma unroll
        for (int k = 0; k < 8; k++) {
            unsigned long long ek2 = pack2(ev[k], ev[k]);
            const ulonglong2* q = (const ulonglong2*)(wp + (k << 6));
#pragma unroll
            for (int j = 0; j < 8; j++) {
                ulonglong2 v = q[j];
                hacc[2 * j]     = fma2(ek2, v.x, hacc[2 * j]);
                hacc[2 * j + 1] = fma2(ek2, v.y, hacc[2 * j + 1]);
            }
        }
#pragma unroll
        for (int j = 0; j < 16; j++) {
            float s0, s1;
            asm("mov.b64 {%0,%1}, %2;" : "=f"(s0), "=f"(s1) : "l"(hacc[j]));
            s0 = silu_f(s0); s1 = silu_f(s1);
            uint32_t hb;
            asm("cvt.rn.bf16x2.f32 %0, %1, %2;" : "=r"(hb) : "f"(s1), "f"(s0));
            float f0 = __uint_as_float(hb << 16);
            float f1 = __uint_as_float(hb & 0xFFFF0000u);
            float r0 = s0 - f0, r1 = s1 - f1;
            uint32_t lb;
            asm("cvt.rn.bf16x2.f32 %0, %1, %2;" : "=r"(lb) : "f"(r1), "f"(r0));
            asm volatile("st.shared.b32 [%0], %1;" :: "r"(hrow + j * 4), "r"(hb) : "memory");
            asm volatile("st.shared.b32 [%0], %1;" :: "r"(hrow + 128 + j * 4), "r"(lb) : "memory");
        }
        __syncwarp();

        // ---- gather contraction with run sharing: load y[src] once per distinct source ----
        {
            int le = 0;
            while (le < 16) {
                int s = ps_w[le];
                const float* b1p = g_y1t + (size_t)s * 96 + lane;
                const float* b2p = g_y2t + (size_t)s * 160 + lane;
                float b0  = __ldg(g_y0 + (size_t)s * 32 + lane);
                float b10 = __ldg(b1p);
                float b11 = __ldg(b1p + 32);
                float b12 = __ldg(b1p + 64);
                float b20 = __ldg(b2p);
                float b21 = __ldg(b2p + 32);
                float b22 = __ldg(b2p + 64);
                float b23 = __ldg(b2p + 96);
                float b24 = __ldg(b2p + 128);
                do {
                    const float* eap = ea_w + le * 9;
                    float z1 = b10 * eap[1];
                    z1 = fmaf(b11, eap[2], z1);
                    z1 = fmaf(b12, eap[3], z1);
                    float z2 = b20 * eap[4];
                    z2 = fmaf(b21, eap[5], z2);
                    z2 = fmaf(b22, eap[6], z2);
                    z2 = fmaf(b23, eap[7], z2);
                    z2 = fmaf(b24, eap[8], z2);
                    zb[le * 100 + lane]      = b0 * eap[0];
                    zb[le * 100 + 32 + lane] = z1;
                    zb[le * 100 + 64 + lane] = z2;
                    le++;
                } while (le < 16 && ps_w[le] == s);
            }
        }
        __syncwarp();

        // ---- GEMM: D[16,96] = Hhi*Whi + Hlo*Whi + Hhi*Wlo ----
        float acc[48];
#pragma unroll
        for (int i = 0; i < 48; i++) acc[i] = 0.f;
#pragma unroll
        for (int k = 0; k < 4; k++) {
            uint32_t ah0, ah1, ah2, ah3, al0, al1, al2, al3;
            asm volatile("ldmatrix.sync.aligned.m8n8.x4.shared.b16 {%0,%1,%2,%3}, [%4];"
                         : "=r"(ah0), "=r"(ah1), "=r"(ah2), "=r"(ah3)
                         : "r"(a_base + k * 32));
            asm volatile("ldmatrix.sync.aligned.m8n8.x4.shared.b16 {%0,%1,%2,%3}, [%4];"
                         : "=r"(al0), "=r"(al1), "=r"(al2), "=r"(al3)
                         : "r"(a_base + 128 + k * 32));
#pragma unroll
            for (int n = 0; n < 12; n++) {
                uint32_t baddr = b_base + (uint32_t)n * 2176 + k * 32;
                uint32_t bh0, bh1, bl0, bl1;
                asm volatile("ldmatrix.sync.aligned.m8n8.x2.shared.b16 {%0,%1}, [%2];"
                             : "=r"(bh0), "=r"(bh1) : "r"(baddr));
                asm volatile("ldmatrix.sync.aligned.m8n8.x2.shared.b16 {%0,%1}, [%2];"
                             : "=r"(bl0), "=r"(bl1) : "r"(baddr + 128));
                float* d = acc + n * 4;
                asm volatile("mma.sync.aligned.m16n8k16.row.col.f32.bf16.bf16.f32 "
                             "{%0,%1,%2,%3}, {%4,%5,%6,%7}, {%8,%9}, {%0,%1,%2,%3};"
                             : "+f"(d[0]), "+f"(d[1]), "+f"(d[2]), "+f"(d[3])
                             : "r"(ah0), "r"(ah1), "r"(ah2), "r"(ah3), "r"(bh0), "r"(bh1));
                asm volatile("mma.sync.aligned.m16n8k16.row.col.f32.bf16.bf16.f32 "
                             "{%0,%1,%2,%3}, {%4,%5,%6,%7}, {%8,%9}, {%0,%1,%2,%3};"
                             : "+f"(d[0]), "+f"(d[1]), "+f"(d[2]), "+f"(d[3])
                             : "r"(al0), "r"(al1), "r"(al2), "r"(al3), "r"(bh0), "r"(bh1));
                asm volatile("mma.sync.aligned.m16n8k16.row.col.f32.bf16.bf16.f32 "
                             "{%0,%1,%2,%3}, {%4,%5,%6,%7}, {%8,%9}, {%0,%1,%2,%3};"
                             : "+f"(d[0]), "+f"(d[1]), "+f"(d[2]), "+f"(d[3])
                             : "r"(ah0), "r"(ah1), "r"(ah2), "r"(ah3), "r"(bl0), "r"(bl1));
            }
        }

        // ---- fused epilogue: multiply D fragment by zbuf in place ----
        {
            int q = lane >> 2, tg = lane & 3;
#pragma unroll
            for (int n = 0; n < 12; n++) {
                int col = n * 8 + tg * 2;
                float2 za = *(float2*)&zb[q * 100 + col];
                float2 zc = *(float2*)&zb[(q + 8) * 100 + col];
                za.x *= acc[n * 4];     za.y *= acc[n * 4 + 1];
                zc.x *= acc[n * 4 + 2]; zc.y *= acc[n * 4 + 3];
                *(float2*)&zb[q * 100 + col]       = za;
                *(float2*)&zb[(q + 8) * 100 + col] = zc;
            }
        }
        __syncwarp();

        // ---- vector atomic scatter (dest random; atomics proven non-binding) ----
        if (lane < 24) {
#pragma unroll 4
            for (int le = 0; le < 16; le++) {
                int d = pd_w[le];
                float4 v = *(const float4*)&zb[le * 100 + lane * 4];
                float* p = &g_mid[(size_t)d * 96 + lane * 4];
                asm volatile("red.global.add.v4.f32 [%0], {%1,%2,%3,%4};"
                             :: "l"(p), "f"(v.x), "f"(v.y), "f"(v.z), "f"(v.w)
                             : "memory");
            }
        }
        __syncwarp();
    }
}

// ---------------- Kernel 3: node finalize ----------------
__global__ void k3_kernel(const float* __restrict__ l2_0,
                          const float* __restrict__ l2_1,
                          const float* __restrict__ l2_2,
                          float* __restrict__ out)
{
    __shared__ __align__(16) float s0t[32 * 36];
    __shared__ __align__(16) float s1t[32 * 68];
    __shared__ __align__(16) float s2t[32 * 100];
    __shared__ __align__(16) float mb[8][96];

    int t = threadIdx.x;
    for (int i = t; i < 1024; i += blockDim.x) { int k = i / 32, w = i % 32; s0t[w * 36 + k]  = l2_0[i]; }
    for (int i = t; i < 2048; i += blockDim.x) { int k = i / 32, w = i % 32; s1t[w * 68 + k]  = l2_1[i]; }
    for (int i = t; i < 3072; i += blockDim.x) { int k = i / 32, w = i % 32; s2t[w * 100 + k] = l2_2[i]; }
    __syncthreads();

    int lane = t & 31;
    int wrp  = t >> 5;
    int n = (int)((blockIdx.x * blockDim.x + t) >> 5);
    if (n >= N_NODES) return;

    mb[wrp][lane]      = g_mid[n * 96 + lane];
    mb[wrp][32 + lane] = g_mid[n * 96 + 32 + lane];
    mb[wrp][64 + lane] = g_mid[n * 96 + 64 + lane];
    __syncwarp();

    unsigned long long A0 = 0ull, A1 = 0ull, A2 = 0ull, B2 = 0ull;
    const float* p0 = &s0t[lane * 36];
    const float* p1 = &s1t[lane * 68];
    const float* p2 = &s2t[lane * 100];
#pragma unroll
    for (int c = 0; c < 24; c++) {
        int k = c * 4;
        ulonglong2 m4 = *(const ulonglong2*)&mb[wrp][k];
        ulonglong2 q2 = *(const ulonglong2*)(p2 + k);
        A2 = fma2(m4.x, q2.x, A2);
        B2 = fma2(m4.y, q2.y, B2);
        if (c < 16) {
            ulonglong2 q1 = *(const ulonglong2*)(p1 + k);
            A1 = fma2(m4.x, q1.x, A1);
            A1 = fma2(m4.y, q1.y, A1);
        }
        if (c < 8) {
            ulonglong2 q0 = *(const ulonglong2*)(p0 + k);
            A0 = fma2(m4.x, q0.x, A0);
            A0 = fma2(m4.y, q0.y, A0);
        }
    }

    const float i32 = 0.17677669529663687f;
    const float i64 = 0.125f;
    const float i96 = 0.10206207261596575f;

    float a0lo, a0hi, a1lo, a1hi, a2lo, a2hi, b2lo, b2hi;
    asm("mov.b64 {%0,%1}, %2;" : "=f"(a0lo), "=f"(a0hi) : "l"(A0));
    asm("mov.b64 {%0,%1}, %2;" : "=f"(a1lo), "=f"(a1hi) : "l"(A1));
    asm("mov.b64 {%0,%1}, %2;" : "=f"(a2lo), "=f"(a2hi) : "l"(A2));
    asm("mov.b64 {%0,%1}, %2;" : "=f"(b2lo), "=f"(b2hi) : "l"(B2));

    float o0 = silu_f(fmaf(a0lo + a0hi, i32, g_sc[                   n * 32 + lane]));
    float o1 = silu_f(fmaf(a1lo + a1hi, i64, g_sc[N_NODES * 32     + n * 32 + lane]));
    float o2 = silu_f(fmaf((a2lo + a2hi) + (b2lo + b2hi), i96, g_sc[2 * N_NODES * 32 + n * 32 + lane]));

    out[                   n * 32 + lane] = o0;
    out[N_NODES * 32     + n * 32 + lane] = o1;
    out[2 * N_NODES * 32  + n * 32 + lane] = o2;
}

// ---------------- launch ----------------
extern "C" void kernel_launch(void* const* d_in, const int* in_sizes, int n_in,
                              void* d_out, int out_size)
{
    const float* x      = (const float*)d_in[0];
    const float* na     = (const float*)d_in[1];
    const float* ee     = (const float*)d_in[2];
    const float* ea     = (const float*)d_in[3];
    const int*   eidx   = (const int*)  d_in[4];
    const float* W1_0   = (const float*)d_in[5];
    const float* W1_1   = (const float*)d_in[6];
    const float* W1_2   = (const float*)d_in[7];
    const float* Wm0    = (const float*)d_in[8];
    const float* Wm1    = (const float*)d_in[9];
    const float* l2_0   = (const float*)d_in[10];
    const float* l2_1   = (const float*)d_in[11];
    const float* l2_2   = (const float*)d_in[12];
    const float* scW    = (const float*)d_in[13];
    float* out = (float*)d_out;

    cudaFuncSetAttribute(k1_kernel, cudaFuncAttributeMaxDynamicSharedMemorySize, 49152);
    cudaFuncSetAttribute(k2_kernel, cudaFuncAttributeMaxDynamicSharedMemorySize, K2_SMEM);

    k0a_zero <<<(N_NODES + 255) / 256, 256>>>();
    k0b_hist <<<(N_EDGES + 255) / 256, 256>>>(eidx);
    k0c_scan <<<1, 1024>>>();
    k0d_place<<<(N_EDGES + 255) / 256, 256>>>(eidx);
    k1_kernel<<<5000, 256, 49152>>>(x, na, W1_0, W1_1, W1_2, scW);
    k2_kernel<<<K2_BLOCKS, 128, K2_SMEM>>>(ee, ea, eidx, Wm0, Wm1);
    k3_kernel<<<2500, 256>>>(l2_0, l2_1, l2_2, out);
    (void)in_sizes; (void)n_in; (void)out_size;
}

// round 10
// speedup vs baseline: 1.1377x; 1.0169x over previous
#include <cuda_runtime.h>
#include <cuda_bf16.h>
#include <cstdint>

#define N_NODES 20000
#define N_EDGES 640000
#define K2_BLOCKS 592
#define K2_SMEM 56064

// ---------------- scratch (static device memory, no allocation) ----------------
__device__ float g_y0 [N_NODES * 32];
__device__ float g_y1t[N_NODES * 3 * 32];
__device__ float g_y2t[N_NODES * 5 * 32];
__device__ float g_sc [3 * N_NODES * 32];
__device__ float g_mid[N_NODES * 96];

__device__ __forceinline__ float silu_f(float x) {
    return __fdividef(x, 1.0f + __expf(-x));
}
__device__ __forceinline__ unsigned long long fma2(unsigned long long a,
                                                   unsigned long long b,
                                                   unsigned long long c) {
    unsigned long long d;
    asm("fma.rn.f32x2 %0, %1, %2, %3;" : "=l"(d) : "l"(a), "l"(b), "l"(c));
    return d;
}
__device__ __forceinline__ unsigned long long pack2(float lo, float hi) {
    unsigned long long p;
    asm("mov.b64 %0, {%1, %2};" : "=l"(p) : "f"(lo), "f"(hi));
    return p;
}
__device__ __forceinline__ uint32_t smem_u32(const void* p) {
    uint32_t a;
    asm("{ .reg .u64 t; cvta.to.shared.u64 t, %1; cvt.u32.u64 %0, t; }" : "=r"(a) : "l"(p));
    return a;
}

// ---------------- Kernel 1 (merged): k1a pre-linear (+zero mid) | k1b self-connection ----------------
__global__ void k1_kernel(const float* __restrict__ x,
                          const float* __restrict__ na,
                          const float* __restrict__ W1_0,
                          const float* __restrict__ W1_1,
                          const float* __restrict__ W1_2,
                          const float* __restrict__ scW)
{
    extern __shared__ __align__(16) float dsm[];
    int t = threadIdx.x;

    if (blockIdx.x < 2500) {
        float* w0s = dsm;
        float* w1s = dsm + 1024;
        float* w2s = dsm + 2048;
        for (int i = t; i < 1024; i += blockDim.x) {
            w0s[i] = W1_0[i]; w1s[i] = W1_1[i]; w2s[i] = W1_2[i];
        }
        __syncthreads();

        int lane = t & 31;
        int n = (int)((blockIdx.x * blockDim.x + t) >> 5);
        if (n >= N_NODES) return;

        const float* xr = x + (size_t)n * 288;
        float x0r = xr[lane];
        float x1r[3], x2r[5];
#pragma unroll
        for (int m = 0; m < 3; m++) x1r[m] = xr[32 + lane * 3 + m];
#pragma unroll
        for (int m = 0; m < 5; m++) x2r[m] = xr[128 + lane * 5 + m];

        float a0 = 0.f;
        float a1[3] = {0.f, 0.f, 0.f};
        float a2[5] = {0.f, 0.f, 0.f, 0.f, 0.f};
#pragma unroll
        for (int u = 0; u < 32; u++) {
            float xv0 = __shfl_sync(0xffffffffu, x0r, u);
            a0 = fmaf(xv0, w0s[u * 32 + lane], a0);
#pragma unroll
            for (int m = 0; m < 3; m++) {
                float xv = __shfl_sync(0xffffffffu, x1r[m], u);
                a1[m] = fmaf(xv, w1s[u * 32 + lane], a1[m]);
            }
#pragma unroll
            for (int m = 0; m < 5; m++) {
                float xv = __shfl_sync(0xffffffffu, x2r[m], u);
                a2[m] = fmaf(xv, w2s[u * 32 + lane], a2[m]);
            }
        }
        const float inv = 0.17677669529663687f;
        g_y0[n * 32 + lane] = a0 * inv;
#pragma unroll
        for (int m = 0; m < 3; m++) g_y1t[(n * 3 + m) * 32 + lane] = a1[m] * inv;
#pragma unroll
        for (int m = 0; m < 5; m++) g_y2t[(n * 5 + m) * 32 + lane] = a2[m] * inv;

        g_mid[n * 96 + lane]      = 0.f;
        g_mid[n * 96 + 32 + lane] = 0.f;
        g_mid[n * 96 + 64 + lane] = 0.f;
    } else {
        float* s = dsm;
        for (int i = t; i < 12288; i += blockDim.x) s[i] = scW[i];
        __syncthreads();

        int lane = t & 31;
        int n = (int)(((blockIdx.x - 2500) * blockDim.x + t) >> 5);
        if (n >= N_NODES) return;

        float x0r = x[(size_t)n * 288 + lane];
        float nar = (lane < 4) ? na[n * 4 + lane] : 0.f;
        float na0 = __shfl_sync(0xffffffffu, nar, 0);
        float na1 = __shfl_sync(0xffffffffu, nar, 1);
        float na2 = __shfl_sync(0xffffffffu, nar, 2);
        float na3 = __shfl_sync(0xffffffffu, nar, 3);

        float acc[3] = {0.f, 0.f, 0.f};
#pragma unroll
        for (int u = 0; u < 32; u++) {
            float x0u = __shfl_sync(0xffffffffu, x0r, u);
            float c0 = x0u * na0, c1 = x0u * na1, c2 = x0u * na2, c3 = x0u * na3;
#pragma unroll
            for (int h = 0; h < 3; h++) {
                const float* p = s + ((h * 32 + u) * 4) * 32 + lane;
                acc[h] = fmaf(c0, p[0],  acc[h]);
                acc[h] = fmaf(c1, p[32], acc[h]);
                acc[h] = fmaf(c2, p[64], acc[h]);
                acc[h] = fmaf(c3, p[96], acc[h]);
            }
        }
        const float invs = 0.08838834764831845f;
#pragma unroll
        for (int h = 0; h < 3; h++)
            g_sc[h * (N_NODES * 32) + n * 32 + lane] = acc[h] * invs;
    }
}

// ---------------- Kernel 2: HMMA edge pipeline, H/zbuf smem union -> 4 blocks/SM ----------------
// 128 threads = 4 independent warps; each warp owns 16 edges per iteration.
// Per-warp union region (6400B): H bf16[16][136] during MLP/GEMM, then z f32[16][100].
// smem: wm0s f32[512] @0 | Wb bf16[96][136] @2048 | union @28160 (4*6400) | ea @53760 (4*576B)
__global__ void __launch_bounds__(128, 4) k2_kernel(const float* __restrict__ ee,
                          const float* __restrict__ ea,
                          const int*   __restrict__ eidx,
                          const float* __restrict__ Wm0,
                          const float* __restrict__ Wm1)
{
    extern __shared__ __align__(16) unsigned char smraw[];
    float*          wm0s = (float*)smraw;                          // [0, 2048)
    __nv_bfloat16*  Wb   = (__nv_bfloat16*)(smraw + 2048);         // [2048, 28160)
    float*          ea_s = (float*)(smraw + 53760);                // [53760, 56064)

    const uint32_t sb    = smem_u32(smraw);
    const uint32_t W_u32 = sb + 2048;
    const uint32_t U_u32 = sb + 28160;

    int tid  = threadIdx.x;
    int lane = tid & 31;
    int wrp  = tid >> 5;

    const float inv8 = 0.35355339059327373f;
    const float C0 = 0.125f * 0.17677669529663687f;
    const float C1 = C0 * 0.5773502691896258f;
    const float C2 = C0 * 0.4472135954999579f;

    for (int i = tid; i < 512; i += 128) wm0s[i] = Wm0[i] * inv8;
    for (int i = tid; i < 96 * 64; i += 128) {
        int n = i >> 6, k = i & 63;
        float Cn = (n < 32) ? C0 : (n < 64) ? C1 : C2;
        float w = Wm1[k * 96 + n] * Cn;
        __nv_bfloat16 hb = __float2bfloat16(w);
        Wb[n * 136 + k]      = hb;
        Wb[n * 136 + 64 + k] = __float2bfloat16(w - __bfloat162float(hb));
    }
    __syncthreads();

    float* ea_w = ea_s + wrp * 144;
    const uint32_t Uw = U_u32 + (uint32_t)wrp * 6400;   // per-warp union region
    float* zb = (float*)(smraw + 28160 + wrp * 6400);

    int eloc = lane >> 1, half = lane & 1;
    const float* wp = wm0s + (half << 5);

    const uint32_t a_base = Uw + (uint32_t)(lane & 15) * 272 + (uint32_t)((lane >> 4) & 1) * 16;
    const uint32_t b_base = W_u32 + (uint32_t)(lane & 7) * 272 + (uint32_t)((lane >> 3) & 1) * 16;
    const uint32_t hrow = Uw + (uint32_t)eloc * 272 + (uint32_t)half * 64;

    int wg = blockIdx.x * 4 + wrp;
    int nw = gridDim.x * 4;

    for (int g = wg; g < N_EDGES / 16; g += nw) {
        int base = g * 16;

        // ---- stage edge attrs (contiguous, coalesced) ----
        for (int i = lane; i < 144; i += 32)
            ea_w[i] = __ldg(ea + (size_t)base * 9 + i);

        // ---- first MLP: 2 lanes per edge, 32 channels each ----
        float ev[8];
        {
            const float4* p = (const float4*)(ee + (size_t)(base + eloc) * 8);
            float4 va = __ldg(p), vb = __ldg(p + 1);
            ev[0]=va.x; ev[1]=va.y; ev[2]=va.z; ev[3]=va.w;
            ev[4]=vb.x; ev[5]=vb.y; ev[6]=vb.z; ev[7]=vb.w;
        }
        unsigned long long hacc[16];
#pragma unroll
        for (int j = 0; j < 16; j++) hacc[j] = 0ull;
#pragma unroll
        for (int k = 0; k < 8; k++) {
            unsigned long long ek2 = pack2(ev[k], ev[k]);
            const ulonglong2* q = (const ulonglong2*)(wp + (k << 6));
#pragma unroll
            for (int j = 0; j < 8; j++) {
                ulonglong2 v = q[j];
                hacc[2 * j]     = fma2(ek2, v.x, hacc[2 * j]);
                hacc[2 * j + 1] = fma2(ek2, v.y, hacc[2 * j + 1]);
            }
        }
        // silu + bf16 split + store H into union region
#pragma unroll
        for (int j = 0; j < 16; j++) {
            float s0, s1;
            asm("mov.b64 {%0,%1}, %2;" : "=f"(s0), "=f"(s1) : "l"(hacc[j]));
            s0 = silu_f(s0); s1 = silu_f(s1);
            uint32_t hb;
            asm("cvt.rn.bf16x2.f32 %0, %1, %2;" : "=r"(hb) : "f"(s1), "f"(s0));
            float f0 = __uint_as_float(hb << 16);
            float f1 = __uint_as_float(hb & 0xFFFF0000u);
            float r0 = s0 - f0, r1 = s1 - f1;
            uint32_t lb;
            asm("cvt.rn.bf16x2.f32 %0, %1, %2;" : "=r"(lb) : "f"(r1), "f"(r0));
            asm volatile("st.shared.b32 [%0], %1;" :: "r"(hrow + j * 4), "r"(hb) : "memory");
            asm volatile("st.shared.b32 [%0], %1;" :: "r"(hrow + 128 + j * 4), "r"(lb) : "memory");
        }
        __syncwarp();

        // ---- GEMM: D[16,96] = Hhi*Whi + Hlo*Whi + Hhi*Wlo (H consumed here) ----
        float acc[48];
#pragma unroll
        for (int i = 0; i < 48; i++) acc[i] = 0.f;
#pragma unroll
        for (int k = 0; k < 4; k++) {
            uint32_t ah0, ah1, ah2, ah3, al0, al1, al2, al3;
            asm volatile("ldmatrix.sync.aligned.m8n8.x4.shared.b16 {%0,%1,%2,%3}, [%4];"
                         : "=r"(ah0), "=r"(ah1), "=r"(ah2), "=r"(ah3)
                         : "r"(a_base + k * 32));
            asm volatile("ldmatrix.sync.aligned.m8n8.x4.shared.b16 {%0,%1,%2,%3}, [%4];"
                         : "=r"(al0), "=r"(al1), "=r"(al2), "=r"(al3)
                         : "r"(a_base + 128 + k * 32));
#pragma unroll
            for (int n = 0; n < 12; n++) {
                uint32_t baddr = b_base + (uint32_t)n * 2176 + k * 32;
                uint32_t bh0, bh1, bl0, bl1;
                asm volatile("ldmatrix.sync.aligned.m8n8.x2.shared.b16 {%0,%1}, [%2];"
                             : "=r"(bh0), "=r"(bh1) : "r"(baddr));
                asm volatile("ldmatrix.sync.aligned.m8n8.x2.shared.b16 {%0,%1}, [%2];"
                             : "=r"(bl0), "=r"(bl1) : "r"(baddr + 128));
                float* d = acc + n * 4;
                asm volatile("mma.sync.aligned.m16n8k16.row.col.f32.bf16.bf16.f32 "
                             "{%0,%1,%2,%3}, {%4,%5,%6,%7}, {%8,%9}, {%0,%1,%2,%3};"
                             : "+f"(d[0]), "+f"(d[1]), "+f"(d[2]), "+f"(d[3])
                             : "r"(ah0), "r"(ah1), "r"(ah2), "r"(ah3), "r"(bh0), "r"(bh1));
                asm volatile("mma.sync.aligned.m16n8k16.row.col.f32.bf16.bf16.f32 "
                             "{%0,%1,%2,%3}, {%4,%5,%6,%7}, {%8,%9}, {%0,%1,%2,%3};"
                             : "+f"(d[0]), "+f"(d[1]), "+f"(d[2]), "+f"(d[3])
                             : "r"(al0), "r"(al1), "r"(al2), "r"(al3), "r"(bh0), "r"(bh1));
                asm volatile("mma.sync.aligned.m16n8k16.row.col.f32.bf16.bf16.f32 "
                             "{%0,%1,%2,%3}, {%4,%5,%6,%7}, {%8,%9}, {%0,%1,%2,%3};"
                             : "+f"(d[0]), "+f"(d[1]), "+f"(d[2]), "+f"(d[3])
                             : "r"(ah0), "r"(ah1), "r"(ah2), "r"(ah3), "r"(bl0), "r"(bl1));
            }
        }
        __syncwarp();   // all ldmatrix reads of H complete before zb overwrites union

        // ---- gather contraction -> zb (aliases dead H region) ----
#pragma unroll
        for (int le = 0; le < 16; le++) {
            int s = __ldg(eidx + base + le);
            const float* eap = ea_w + le * 9;
            float y0v = __ldg(g_y0 + (size_t)s * 32 + lane);
            float z1 = __ldg(g_y1t + (size_t)s * 96 + lane) * eap[1];
            z1 = fmaf(__ldg(g_y1t + (size_t)s * 96 + 32 + lane), eap[2], z1);
            z1 = fmaf(__ldg(g_y1t + (size_t)s * 96 + 64 + lane), eap[3], z1);
            float z2 = __ldg(g_y2t + (size_t)s * 160 + lane) * eap[4];
            z2 = fmaf(__ldg(g_y2t + (size_t)s * 160 + 32 + lane),  eap[5], z2);
            z2 = fmaf(__ldg(g_y2t + (size_t)s * 160 + 64 + lane),  eap[6], z2);
            z2 = fmaf(__ldg(g_y2t + (size_t)s * 160 + 96 + lane),  eap[7], z2);
            z2 = fmaf(__ldg(g_y2t + (size_t)s * 160 + 128 + lane), eap[8], z2);

            zb[le * 100 + lane]      = y0v * eap[0];
            zb[le * 100 + 32 + lane] = z1;
            zb[le * 100 + 64 + lane] = z2;
        }
        __syncwarp();

        // ---- fused epilogue: multiply D fragment by zb in place ----
        {
            int q = lane >> 2, tg = lane & 3;
#pragma unroll
            for (int n = 0; n < 12; n++) {
                int col = n * 8 + tg * 2;
                float2 za = *(float2*)&zb[q * 100 + col];
                float2 zc = *(float2*)&zb[(q + 8) * 100 + col];
                za.x *= acc[n * 4];     za.y *= acc[n * 4 + 1];
                zc.x *= acc[n * 4 + 2]; zc.y *= acc[n * 4 + 3];
                *(float2*)&zb[q * 100 + col]       = za;
                *(float2*)&zb[(q + 8) * 100 + col] = zc;
            }
        }
        __syncwarp();

        // ---- vector atomic scatter ----
        if (lane < 24) {
#pragma unroll 4
            for (int le = 0; le < 16; le++) {
                int d = __ldg(eidx + N_EDGES + base + le);
                float4 v = *(const float4*)&zb[le * 100 + lane * 4];
                float* p = &g_mid[(size_t)d * 96 + lane * 4];
                asm volatile("red.global.add.v4.f32 [%0], {%1,%2,%3,%4};"
                             :: "l"(p), "f"(v.x), "f"(v.y), "f"(v.z), "f"(v.w)
                             : "memory");
            }
        }
        __syncwarp();
    }
}

// ---------------- Kernel 3: node finalize ----------------
__global__ void k3_kernel(const float* __restrict__ l2_0,
                          const float* __restrict__ l2_1,
                          const float* __restrict__ l2_2,
                          float* __restrict__ out)
{
    __shared__ __align__(16) float s0t[32 * 36];
    __shared__ __align__(16) float s1t[32 * 68];
    __shared__ __align__(16) float s2t[32 * 100];
    __shared__ __align__(16) float mb[8][96];

    int t = threadIdx.x;
    for (int i = t; i < 1024; i += blockDim.x) { int k = i / 32, w = i % 32; s0t[w * 36 + k]  = l2_0[i]; }
    for (int i = t; i < 2048; i += blockDim.x) { int k = i / 32, w = i % 32; s1t[w * 68 + k]  = l2_1[i]; }
    for (int i = t; i < 3072; i += blockDim.x) { int k = i / 32, w = i % 32; s2t[w * 100 + k] = l2_2[i]; }
    __syncthreads();

    int lane = t & 31;
    int wrp  = t >> 5;
    int n = (int)((blockIdx.x * blockDim.x + t) >> 5);
    if (n >= N_NODES) return;

    mb[wrp][lane]      = g_mid[n * 96 + lane];
    mb[wrp][32 + lane] = g_mid[n * 96 + 32 + lane];
    mb[wrp][64 + lane] = g_mid[n * 96 + 64 + lane];
    __syncwarp();

    unsigned long long A0 = 0ull, A1 = 0ull, A2 = 0ull, B2 = 0ull;
    const float* p0 = &s0t[lane * 36];
    const float* p1 = &s1t[lane * 68];
    const float* p2 = &s2t[lane * 100];
#pragma unroll
    for (int c = 0; c < 24; c++) {
        int k = c * 4;
        ulonglong2 m4 = *(const ulonglong2*)&mb[wrp][k];
        ulonglong2 q2 = *(const ulonglong2*)(p2 + k);
        A2 = fma2(m4.x, q2.x, A2);
        B2 = fma2(m4.y, q2.y, B2);
        if (c < 16) {
            ulonglong2 q1 = *(const ulonglong2*)(p1 + k);
            A1 = fma2(m4.x, q1.x, A1);
            A1 = fma2(m4.y, q1.y, A1);
        }
        if (c < 8) {
            ulonglong2 q0 = *(const ulonglong2*)(p0 + k);
            A0 = fma2(m4.x, q0.x, A0);
            A0 = fma2(m4.y, q0.y, A0);
        }
    }

    const float i32 = 0.17677669529663687f;
    const float i64 = 0.125f;
    const float i96 = 0.10206207261596575f;

    float a0lo, a0hi, a1lo, a1hi, a2lo, a2hi, b2lo, b2hi;
    asm("mov.b64 {%0,%1}, %2;" : "=f"(a0lo), "=f"(a0hi) : "l"(A0));
    asm("mov.b64 {%0,%1}, %2;" : "=f"(a1lo), "=f"(a1hi) : "l"(A1));
    asm("mov.b64 {%0,%1}, %2;" : "=f"(a2lo), "=f"(a2hi) : "l"(A2));
    asm("mov.b64 {%0,%1}, %2;" : "=f"(b2lo), "=f"(b2hi) : "l"(B2));

    float o0 = silu_f(fmaf(a0lo + a0hi, i32, g_sc[                   n * 32 + lane]));
    float o1 = silu_f(fmaf(a1lo + a1hi, i64, g_sc[N_NODES * 32     + n * 32 + lane]));
    float o2 = silu_f(fmaf((a2lo + a2hi) + (b2lo + b2hi), i96, g_sc[2 * N_NODES * 32 + n * 32 + lane]));

    out[                   n * 32 + lane] = o0;
    out[N_NODES * 32     + n * 32 + lane] = o1;
    out[2 * N_NODES * 32  + n * 32 + lane] = o2;
}

// ---------------- launch ----------------
extern "C" void kernel_launch(void* const* d_in, const int* in_sizes, int n_in,
                              void* d_out, int out_size)
{
    const float* x      = (const float*)d_in[0];
    const float* na     = (const float*)d_in[1];
    const float* ee     = (const float*)d_in[2];
    const float* ea     = (const float*)d_in[3];
    const int*   eidx   = (const int*)  d_in[4];
    const float* W1_0   = (const float*)d_in[5];
    const float* W1_1   = (const float*)d_in[6];
    const float* W1_2   = (const float*)d_in[7];
    const float* Wm0    = (const float*)d_in[8];
    const float* Wm1    = (const float*)d_in[9];
    const float* l2_0   = (const float*)d_in[10];
    const float* l2_1   = (const float*)d_in[11];
    const float* l2_2   = (const float*)d_in[12];
    const float* scW    = (const float*)d_in[13];
    float* out = (float*)d_out;

    cudaFuncSetAttribute(k1_kernel, cudaFuncAttributeMaxDynamicSharedMemorySize, 49152);
    cudaFuncSetAttribute(k2_kernel, cudaFuncAttributeMaxDynamicSharedMemorySize, K2_SMEM);

    k1_kernel<<<5000, 256, 49152>>>(x, na, W1_0, W1_1, W1_2, scW);
    k2_kernel<<<K2_BLOCKS, 128, K2_SMEM>>>(ee, ea, eidx, Wm0, Wm1);
    k3_kernel<<<2500, 256>>>(l2_0, l2_1, l2_2, out);
    (void)in_sizes; (void)n_in; (void)out_size;
}

// round 11
// speedup vs baseline: 1.3422x; 1.1798x over previous
#include <cuda_runtime.h>
#include <cuda_bf16.h>
#include <cstdint>

#define N_NODES 20000
#define N_EDGES 640000
#define K2_BLOCKS 444
#define K2_SMEM 73472

// ---------------- scratch (static device memory, no allocation) ----------------
__device__ float g_y0 [N_NODES * 32];
__device__ float g_y1t[N_NODES * 3 * 32];
__device__ float g_y2t[N_NODES * 5 * 32];
__device__ float g_sc [3 * N_NODES * 32];
__device__ float g_mid[N_NODES * 96];

__device__ __forceinline__ float silu_f(float x) {
    return __fdividef(x, 1.0f + __expf(-x));
}
__device__ __forceinline__ unsigned long long fma2(unsigned long long a,
                                                   unsigned long long b,
                                                   unsigned long long c) {
    unsigned long long d;
    asm("fma.rn.f32x2 %0, %1, %2, %3;" : "=l"(d) : "l"(a), "l"(b), "l"(c));
    return d;
}
__device__ __forceinline__ unsigned long long pack2(float lo, float hi) {
    unsigned long long p;
    asm("mov.b64 %0, {%1, %2};" : "=l"(p) : "f"(lo), "f"(hi));
    return p;
}
__device__ __forceinline__ uint32_t smem_u32(const void* p) {
    uint32_t a;
    asm("{ .reg .u64 t; cvta.to.shared.u64 t, %1; cvt.u32.u64 %0, t; }" : "=r"(a) : "l"(p));
    return a;
}

// ---------------- Kernel 1 (merged): 2 nodes per warp for ILP ----------------
// blocks [0,1250): k1a pre-linear + zero mid; blocks [1250,2500): k1b self-connection
__global__ void k1_kernel(const float* __restrict__ x,
                          const float* __restrict__ na,
                          const float* __restrict__ W1_0,
                          const float* __restrict__ W1_1,
                          const float* __restrict__ W1_2,
                          const float* __restrict__ scW)
{
    extern __shared__ __align__(16) float dsm[];
    int t = threadIdx.x;
    int lane = t & 31;
    int wrp  = t >> 5;

    if (blockIdx.x < 1250) {
        // ------- k1a: y0/y1/y2 pre-linear + zero mid (2 nodes/warp) -------
        float* w0s = dsm;
        float* w1s = dsm + 1024;
        float* w2s = dsm + 2048;
        for (int i = t; i < 1024; i += blockDim.x) {
            w0s[i] = W1_0[i]; w1s[i] = W1_1[i]; w2s[i] = W1_2[i];
        }
        __syncthreads();

        int n0 = (blockIdx.x * 8 + wrp) * 2;   // nodes n0, n0+1 (< 20000 always)

        const float* xa = x + (size_t)n0 * 288;
        const float* xb = xa + 288;
        float x0a = xa[lane],  x0b = xb[lane];
        float x1a[3], x1b[3], x2a[5], x2b[5];
#pragma unroll
        for (int m = 0; m < 3; m++) { x1a[m] = xa[32 + lane * 3 + m]; x1b[m] = xb[32 + lane * 3 + m]; }
#pragma unroll
        for (int m = 0; m < 5; m++) { x2a[m] = xa[128 + lane * 5 + m]; x2b[m] = xb[128 + lane * 5 + m]; }

        float a0a = 0.f, a0b = 0.f;
        float a1a[3] = {0.f,0.f,0.f}, a1b[3] = {0.f,0.f,0.f};
        float a2a[5] = {0.f,0.f,0.f,0.f,0.f}, a2b[5] = {0.f,0.f,0.f,0.f,0.f};
#pragma unroll
        for (int u = 0; u < 32; u++) {
            float w0 = w0s[u * 32 + lane];
            float w1 = w1s[u * 32 + lane];
            float w2 = w2s[u * 32 + lane];
            a0a = fmaf(__shfl_sync(0xffffffffu, x0a, u), w0, a0a);
            a0b = fmaf(__shfl_sync(0xffffffffu, x0b, u), w0, a0b);
#pragma unroll
            for (int m = 0; m < 3; m++) {
                a1a[m] = fmaf(__shfl_sync(0xffffffffu, x1a[m], u), w1, a1a[m]);
                a1b[m] = fmaf(__shfl_sync(0xffffffffu, x1b[m], u), w1, a1b[m]);
            }
#pragma unroll
            for (int m = 0; m < 5; m++) {
                a2a[m] = fmaf(__shfl_sync(0xffffffffu, x2a[m], u), w2, a2a[m]);
                a2b[m] = fmaf(__shfl_sync(0xffffffffu, x2b[m], u), w2, a2b[m]);
            }
        }
        const float inv = 0.17677669529663687f; // 1/sqrt(32)
        g_y0[n0 * 32 + lane]       = a0a * inv;
        g_y0[(n0 + 1) * 32 + lane] = a0b * inv;
#pragma unroll
        for (int m = 0; m < 3; m++) {
            g_y1t[(n0 * 3 + m) * 32 + lane]       = a1a[m] * inv;
            g_y1t[((n0 + 1) * 3 + m) * 32 + lane] = a1b[m] * inv;
        }
#pragma unroll
        for (int m = 0; m < 5; m++) {
            g_y2t[(n0 * 5 + m) * 32 + lane]       = a2a[m] * inv;
            g_y2t[((n0 + 1) * 5 + m) * 32 + lane] = a2b[m] * inv;
        }
#pragma unroll
        for (int j = 0; j < 3; j++) {
            g_mid[n0 * 96 + j * 32 + lane]       = 0.f;
            g_mid[(n0 + 1) * 96 + j * 32 + lane] = 0.f;
        }
    } else {
        // ------- k1b: self-connection sc (2 nodes/warp) -------
        float* s = dsm; // 12288 floats = 48KB
        for (int i = t; i < 12288; i += blockDim.x) s[i] = scW[i];
        __syncthreads();

        int n0 = ((blockIdx.x - 1250) * 8 + wrp) * 2;

        float x0a = x[(size_t)n0 * 288 + lane];
        float x0b = x[(size_t)(n0 + 1) * 288 + lane];
        float naa = (lane < 4) ? na[n0 * 4 + lane] : 0.f;
        float nab = (lane < 4) ? na[(n0 + 1) * 4 + lane] : 0.f;
        float na0a = __shfl_sync(0xffffffffu, naa, 0);
        float na1a = __shfl_sync(0xffffffffu, naa, 1);
        float na2a = __shfl_sync(0xffffffffu, naa, 2);
        float na3a = __shfl_sync(0xffffffffu, naa, 3);
        float na0b = __shfl_sync(0xffffffffu, nab, 0);
        float na1b = __shfl_sync(0xffffffffu, nab, 1);
        float na2b = __shfl_sync(0xffffffffu, nab, 2);
        float na3b = __shfl_sync(0xffffffffu, nab, 3);

        float acca[3] = {0.f, 0.f, 0.f};
        float accb[3] = {0.f, 0.f, 0.f};
#pragma unroll
        for (int u = 0; u < 32; u++) {
            float xua = __shfl_sync(0xffffffffu, x0a, u);
            float xub = __shfl_sync(0xffffffffu, x0b, u);
            float c0a = xua * na0a, c1a = xua * na1a, c2a = xua * na2a, c3a = xua * na3a;
            float c0b = xub * na0b, c1b = xub * na1b, c2b = xub * na2b, c3b = xub * na3b;
#pragma unroll
            for (int h = 0; h < 3; h++) {
                const float* p = s + ((h * 32 + u) * 4) * 32 + lane;
                float p0 = p[0], p1 = p[32], p2 = p[64], p3 = p[96];
                acca[h] = fmaf(c0a, p0, acca[h]);
                accb[h] = fmaf(c0b, p0, accb[h]);
                acca[h] = fmaf(c1a, p1, acca[h]);
                accb[h] = fmaf(c1b, p1, accb[h]);
                acca[h] = fmaf(c2a, p2, acca[h]);
                accb[h] = fmaf(c2b, p2, accb[h]);
                acca[h] = fmaf(c3a, p3, acca[h]);
                accb[h] = fmaf(c3b, p3, accb[h]);
            }
        }
        const float invs = 0.08838834764831845f; // 1/sqrt(128)
#pragma unroll
        for (int h = 0; h < 3; h++) {
            g_sc[h * (N_NODES * 32) + n0 * 32 + lane]       = acca[h] * invs;
            g_sc[h * (N_NODES * 32) + (n0 + 1) * 32 + lane] = accb[h] * invs;
        }
    }
}

// ---------------- Kernel 2: HMMA bf16-split edge pipeline, gather hoisted (R7 config) ----------------
// 128 threads = 4 independent warps; each warp owns 16 edges per iteration.
// smem: wm0s f32[512] | W bf16[96][136] | H bf16[4][16][136] | zbuf f32[4][16][100] | ea f32[4][144]
__global__ void __launch_bounds__(128, 3) k2_kernel(const float* __restrict__ ee,
                          const float* __restrict__ ea,
                          const int*   __restrict__ eidx,
                          const float* __restrict__ Wm0,
                          const float* __restrict__ Wm1)
{
    extern __shared__ __align__(16) unsigned char smraw[];
    float*          wm0s = (float*)smraw;                          // [0, 2048)
    __nv_bfloat16*  Wb   = (__nv_bfloat16*)(smraw + 2048);         // [2048, 28160)
    float*          zbuf = (float*)(smraw + 45568);                // [45568, 71168)
    float*          ea_s = (float*)(smraw + 71168);                // [71168, 73472)

    const uint32_t sb    = smem_u32(smraw);
    const uint32_t W_u32 = sb + 2048;
    const uint32_t H_u32 = sb + 28160;

    int tid  = threadIdx.x;
    int lane = tid & 31;
    int wrp  = tid >> 5;

    const float inv8 = 0.35355339059327373f;
    const float C0 = 0.125f * 0.17677669529663687f;
    const float C1 = C0 * 0.5773502691896258f;
    const float C2 = C0 * 0.4472135954999579f;

    for (int i = tid; i < 512; i += 128) wm0s[i] = Wm0[i] * inv8;
    for (int i = tid; i < 96 * 64; i += 128) {
        int n = i >> 6, k = i & 63;
        float Cn = (n < 32) ? C0 : (n < 64) ? C1 : C2;
        float w = Wm1[k * 96 + n] * Cn;
        __nv_bfloat16 hb = __float2bfloat16(w);
        Wb[n * 136 + k]      = hb;
        Wb[n * 136 + 64 + k] = __float2bfloat16(w - __bfloat162float(hb));
    }
    __syncthreads();

    float* ea_w = ea_s + wrp * 144;
    float* zb   = zbuf + wrp * 1600;
    const uint32_t Hw = H_u32 + wrp * 4352;

    int eloc = lane >> 1, half = lane & 1;
    const float* wp = wm0s + (half << 5);

    const uint32_t a_base = Hw + (uint32_t)(lane & 15) * 272 + (uint32_t)((lane >> 4) & 1) * 16;
    const uint32_t b_base = W_u32 + (uint32_t)(lane & 7) * 272 + (uint32_t)((lane >> 3) & 1) * 16;
    const uint32_t hrow = Hw + (uint32_t)eloc * 272 + (uint32_t)half * 64;

    int wg = blockIdx.x * 4 + wrp;
    int nw = gridDim.x * 4;

    for (int g = wg; g < N_EDGES / 16; g += nw) {
        int base = g * 16;

        // ---- stage edge attrs ----
        for (int i = lane; i < 144; i += 32)
            ea_w[i] = __ldg(ea + (size_t)base * 9 + i);

        // ---- first MLP: 2 lanes per edge ----
        float ev[8];
        {
            const float4* p = (const float4*)(ee + (size_t)(base + eloc) * 8);
            float4 va = __ldg(p), vb = __ldg(p + 1);
            ev[0]=va.x; ev[1]=va.y; ev[2]=va.z; ev[3]=va.w;
            ev[4]=vb.x; ev[5]=vb.y; ev[6]=vb.z; ev[7]=vb.w;
        }
        unsigned long long hacc[16];
#pragma unroll
        for (int j = 0; j < 16; j++) hacc[j] = 0ull;
#pragma unroll
        for (int k = 0; k < 8; k++) {
            unsigned long long ek2 = pack2(ev[k], ev[k]);
            const ulonglong2* q = (const ulonglong2*)(wp + (k << 6));
#pragma unroll
            for (int j = 0; j < 8; j++) {
                ulonglong2 v = q[j];
                hacc[2 * j]     = fma2(ek2, v.x, hacc[2 * j]);
                hacc[2 * j + 1] = fma2(ek2, v.y, hacc[2 * j + 1]);
            }
        }
#pragma unroll
        for (int j = 0; j < 16; j++) {
            float s0, s1;
            asm("mov.b64 {%0,%1}, %2;" : "=f"(s0), "=f"(s1) : "l"(hacc[j]));
            s0 = silu_f(s0); s1 = silu_f(s1);
            uint32_t hb;
            asm("cvt.rn.bf16x2.f32 %0, %1, %2;" : "=r"(hb) : "f"(s1), "f"(s0));
            float f0 = __uint_as_float(hb << 16);
            float f1 = __uint_as_float(hb & 0xFFFF0000u);
            float r0 = s0 - f0, r1 = s1 - f1;
            uint32_t lb;
            asm("cvt.rn.bf16x2.f32 %0, %1, %2;" : "=r"(lb) : "f"(r1), "f"(r0));
            asm volatile("st.shared.b32 [%0], %1;" :: "r"(hrow + j * 4), "r"(hb) : "memory");
            asm volatile("st.shared.b32 [%0], %1;" :: "r"(hrow + 128 + j * 4), "r"(lb) : "memory");
        }
        __syncwarp();

        // ---- hoisted gather contraction -> zbuf (independent of GEMM) ----
#pragma unroll
        for (int le = 0; le < 16; le++) {
            int s = __ldg(eidx + base + le);
            const float* eap = ea_w + le * 9;
            float y0v = __ldg(g_y0 + (size_t)s * 32 + lane);
            float z1 = __ldg(g_y1t + (size_t)s * 96 + lane) * eap[1];
            z1 = fmaf(__ldg(g_y1t + (size_t)s * 96 + 32 + lane), eap[2], z1);
            z1 = fmaf(__ldg(g_y1t + (size_t)s * 96 + 64 + lane), eap[3], z1);
            float z2 = __ldg(g_y2t + (size_t)s * 160 + lane) * eap[4];
            z2 = fmaf(__ldg(g_y2t + (size_t)s * 160 + 32 + lane),  eap[5], z2);
            z2 = fmaf(__ldg(g_y2t + (size_t)s * 160 + 64 + lane),  eap[6], z2);
            z2 = fmaf(__ldg(g_y2t + (size_t)s * 160 + 96 + lane),  eap[7], z2);
            z2 = fmaf(__ldg(g_y2t + (size_t)s * 160 + 128 + lane), eap[8], z2);

            zb[le * 100 + lane]      = y0v * eap[0];
            zb[le * 100 + 32 + lane] = z1;
            zb[le * 100 + 64 + lane] = z2;
        }
        __syncwarp();

        // ---- GEMM: D[16,96] = Hhi*Whi + Hlo*Whi + Hhi*Wlo ----
        float acc[48];
#pragma unroll
        for (int i = 0; i < 48; i++) acc[i] = 0.f;
#pragma unroll
        for (int k = 0; k < 4; k++) {
            uint32_t ah0, ah1, ah2, ah3, al0, al1, al2, al3;
            asm volatile("ldmatrix.sync.aligned.m8n8.x4.shared.b16 {%0,%1,%2,%3}, [%4];"
                         : "=r"(ah0), "=r"(ah1), "=r"(ah2), "=r"(ah3)
                         : "r"(a_base + k * 32));
            asm volatile("ldmatrix.sync.aligned.m8n8.x4.shared.b16 {%0,%1,%2,%3}, [%4];"
                         : "=r"(al0), "=r"(al1), "=r"(al2), "=r"(al3)
                         : "r"(a_base + 128 + k * 32));
#pragma unroll
            for (int n = 0; n < 12; n++) {
                uint32_t baddr = b_base + (uint32_t)n * 2176 + k * 32;
                uint32_t bh0, bh1, bl0, bl1;
                asm volatile("ldmatrix.sync.aligned.m8n8.x2.shared.b16 {%0,%1}, [%2];"
                             : "=r"(bh0), "=r"(bh1) : "r"(baddr));
                asm volatile("ldmatrix.sync.aligned.m8n8.x2.shared.b16 {%0,%1}, [%2];"
                             : "=r"(bl0), "=r"(bl1) : "r"(baddr + 128));
                float* d = acc + n * 4;
                asm volatile("mma.sync.aligned.m16n8k16.row.col.f32.bf16.bf16.f32 "
                             "{%0,%1,%2,%3}, {%4,%5,%6,%7}, {%8,%9}, {%0,%1,%2,%3};"
                             : "+f"(d[0]), "+f"(d[1]), "+f"(d[2]), "+f"(d[3])
                             : "r"(ah0), "r"(ah1), "r"(ah2), "r"(ah3), "r"(bh0), "r"(bh1));
                asm volatile("mma.sync.aligned.m16n8k16.row.col.f32.bf16.bf16.f32 "
                             "{%0,%1,%2,%3}, {%4,%5,%6,%7}, {%8,%9}, {%0,%1,%2,%3};"
                             : "+f"(d[0]), "+f"(d[1]), "+f"(d[2]), "+f"(d[3])
                             : "r"(al0), "r"(al1), "r"(al2), "r"(al3), "r"(bh0), "r"(bh1));
                asm volatile("mma.sync.aligned.m16n8k16.row.col.f32.bf16.bf16.f32 "
                             "{%0,%1,%2,%3}, {%4,%5,%6,%7}, {%8,%9}, {%0,%1,%2,%3};"
                             : "+f"(d[0]), "+f"(d[1]), "+f"(d[2]), "+f"(d[3])
                             : "r"(ah0), "r"(ah1), "r"(ah2), "r"(ah3), "r"(bl0), "r"(bl1));
            }
        }

        // ---- fused epilogue: multiply D fragment by zbuf in place ----
        {
            int q = lane >> 2, tg = lane & 3;
#pragma unroll
            for (int n = 0; n < 12; n++) {
                int col = n * 8 + tg * 2;
                float2 za = *(float2*)&zb[q * 100 + col];
                float2 zc = *(float2*)&zb[(q + 8) * 100 + col];
                za.x *= acc[n * 4];     za.y *= acc[n * 4 + 1];
                zc.x *= acc[n * 4 + 2]; zc.y *= acc[n * 4 + 3];
                *(float2*)&zb[q * 100 + col]       = za;
                *(float2*)&zb[(q + 8) * 100 + col] = zc;
            }
        }
        __syncwarp();

        // ---- vector atomic scatter ----
        if (lane < 24) {
#pragma unroll 4
            for (int le = 0; le < 16; le++) {
                int d = __ldg(eidx + N_EDGES + base + le);
                float4 v = *(const float4*)&zb[le * 100 + lane * 4];
                float* p = &g_mid[(size_t)d * 96 + lane * 4];
                asm volatile("red.global.add.v4.f32 [%0], {%1,%2,%3,%4};"
                             :: "l"(p), "f"(v.x), "f"(v.y), "f"(v.z), "f"(v.w)
                             : "memory");
            }
        }
        __syncwarp();
    }
}

// ---------------- Kernel 3: node finalize ----------------
__global__ void k3_kernel(const float* __restrict__ l2_0,
                          const float* __restrict__ l2_1,
                          const float* __restrict__ l2_2,
                          float* __restrict__ out)
{
    __shared__ __align__(16) float s0t[32 * 36];
    __shared__ __align__(16) float s1t[32 * 68];
    __shared__ __align__(16) float s2t[32 * 100];
    __shared__ __align__(16) float mb[8][96];

    int t = threadIdx.x;
    for (int i = t; i < 1024; i += blockDim.x) { int k = i / 32, w = i % 32; s0t[w * 36 + k]  = l2_0[i]; }
    for (int i = t; i < 2048; i += blockDim.x) { int k = i / 32, w = i % 32; s1t[w * 68 + k]  = l2_1[i]; }
    for (int i = t; i < 3072; i += blockDim.x) { int k = i / 32, w = i % 32; s2t[w * 100 + k] = l2_2[i]; }
    __syncthreads();

    int lane = t & 31;
    int wrp  = t >> 5;
    int n = (int)((blockIdx.x * blockDim.x + t) >> 5);
    if (n >= N_NODES) return;

    mb[wrp][lane]      = g_mid[n * 96 + lane];
    mb[wrp][32 + lane] = g_mid[n * 96 + 32 + lane];
    mb[wrp][64 + lane] = g_mid[n * 96 + 64 + lane];
    __syncwarp();

    unsigned long long A0 = 0ull, A1 = 0ull, A2 = 0ull, B2 = 0ull;
    const float* p0 = &s0t[lane * 36];
    const float* p1 = &s1t[lane * 68];
    const float* p2 = &s2t[lane * 100];
#pragma unroll
    for (int c = 0; c < 24; c++) {
        int k = c * 4;
        ulonglong2 m4 = *(const ulonglong2*)&mb[wrp][k];
        ulonglong2 q2 = *(const ulonglong2*)(p2 + k);
        A2 = fma2(m4.x, q2.x, A2);
        B2 = fma2(m4.y, q2.y, B2);
        if (c < 16) {
            ulonglong2 q1 = *(const ulonglong2*)(p1 + k);
            A1 = fma2(m4.x, q1.x, A1);
            A1 = fma2(m4.y, q1.y, A1);
        }
        if (c < 8) {
            ulonglong2 q0 = *(const ulonglong2*)(p0 + k);
            A0 = fma2(m4.x, q0.x, A0);
            A0 = fma2(m4.y, q0.y, A0);
        }
    }

    const float i32 = 0.17677669529663687f;
    const float i64 = 0.125f;
    const float i96 = 0.10206207261596575f;

    float a0lo, a0hi, a1lo, a1hi, a2lo, a2hi, b2lo, b2hi;
    asm("mov.b64 {%0,%1}, %2;" : "=f"(a0lo), "=f"(a0hi) : "l"(A0));
    asm("mov.b64 {%0,%1}, %2;" : "=f"(a1lo), "=f"(a1hi) : "l"(A1));
    asm("mov.b64 {%0,%1}, %2;" : "=f"(a2lo), "=f"(a2hi) : "l"(A2));
    asm("mov.b64 {%0,%1}, %2;" : "=f"(b2lo), "=f"(b2hi) : "l"(B2));

    float o0 = silu_f(fmaf(a0lo + a0hi, i32, g_sc[                   n * 32 + lane]));
    float o1 = silu_f(fmaf(a1lo + a1hi, i64, g_sc[N_NODES * 32     + n * 32 + lane]));
    float o2 = silu_f(fmaf((a2lo + a2hi) + (b2lo + b2hi), i96, g_sc[2 * N_NODES * 32 + n * 32 + lane]));

    out[                   n * 32 + lane] = o0;
    out[N_NODES * 32     + n * 32 + lane] = o1;
    out[2 * N_NODES * 32  + n * 32 + lane] = o2;
}

// ---------------- launch ----------------
extern "C" void kernel_launch(void* const* d_in, const int* in_sizes, int n_in,
                              void* d_out, int out_size)
{
    const float* x      = (const float*)d_in[0];
    const float* na     = (const float*)d_in[1];
    const float* ee     = (const float*)d_in[2];
    const float* ea     = (const float*)d_in[3];
    const int*   eidx   = (const int*)  d_in[4];
    const float* W1_0   = (const float*)d_in[5];
    const float* W1_1   = (const float*)d_in[6];
    const float* W1_2   = (const float*)d_in[7];
    const float* Wm0    = (const float*)d_in[8];
    const float* Wm1    = (const float*)d_in[9];
    const float* l2_0   = (const float*)d_in[10];
    const float* l2_1   = (const float*)d_in[11];
    const float* l2_2   = (const float*)d_in[12];
    const float* scW    = (const float*)d_in[13];
    float* out = (float*)d_out;

    cudaFuncSetAttribute(k1_kernel, cudaFuncAttributeMaxDynamicSharedMemorySize, 49152);
    cudaFuncSetAttribute(k2_kernel, cudaFuncAttributeMaxDynamicSharedMemorySize, K2_SMEM);

    k1_kernel<<<2500, 256, 49152>>>(x, na, W1_0, W1_1, W1_2, scW);
    k2_kernel<<<K2_BLOCKS, 128, K2_SMEM>>>(ee, ea, eidx, Wm0, Wm1);
    k3_kernel<<<2500, 256>>>(l2_0, l2_1, l2_2, out);
    (void)in_sizes; (void)n_in; (void)out_size;
}

// round 12
// speedup vs baseline: 1.3832x; 1.0306x over previous
#include <cuda_runtime.h>
#include <cuda_bf16.h>
#include <cstdint>

#define N_NODES 20000
#define N_EDGES 640000
#define K2_BLOCKS 444
#define K2_SMEM 73472

// ---------------- scratch (static device memory, no allocation) ----------------
__device__ float g_y0 [N_NODES * 32];
__device__ float g_y1t[N_NODES * 3 * 32];
__device__ float g_y2t[N_NODES * 5 * 32];
__device__ float g_sc [3 * N_NODES * 32];
__device__ float g_mid[N_NODES * 96];

__device__ __forceinline__ float silu_f(float x) {
    return __fdividef(x, 1.0f + __expf(-x));
}
__device__ __forceinline__ unsigned long long fma2(unsigned long long a,
                                                   unsigned long long b,
                                                   unsigned long long c) {
    unsigned long long d;
    asm("fma.rn.f32x2 %0, %1, %2, %3;" : "=l"(d) : "l"(a), "l"(b), "l"(c));
    return d;
}
__device__ __forceinline__ unsigned long long pack2(float lo, float hi) {
    unsigned long long p;
    asm("mov.b64 %0, {%1, %2};" : "=l"(p) : "f"(lo), "f"(hi));
    return p;
}
__device__ __forceinline__ uint32_t smem_u32(const void* p) {
    uint32_t a;
    asm("{ .reg .u64 t; cvta.to.shared.u64 t, %1; cvt.u32.u64 %0, t; }" : "=r"(a) : "l"(p));
    return a;
}

// ---------------- Kernel 1 (merged): 2 nodes per warp + smem-staged x rows ----------------
// blocks [0,1250): k1a pre-linear + zero mid; blocks [1250,2500): k1b self-connection
__global__ void k1_kernel(const float* __restrict__ x,
                          const float* __restrict__ na,
                          const float* __restrict__ W1_0,
                          const float* __restrict__ W1_1,
                          const float* __restrict__ W1_2,
                          const float* __restrict__ scW)
{
    extern __shared__ __align__(16) float dsm[];
    int t = threadIdx.x;
    int lane = t & 31;
    int wrp  = t >> 5;

    if (blockIdx.x < 1250) {
        // ------- k1a: y0/y1/y2 pre-linear + zero mid (2 nodes/warp) -------
        float* w0s = dsm;
        float* w1s = dsm + 1024;
        float* w2s = dsm + 2048;
        float* xs  = dsm + 3072 + wrp * 576;   // per-warp 2x288 staged rows
        for (int i = t; i < 1024; i += blockDim.x) {
            w0s[i] = W1_0[i]; w1s[i] = W1_1[i]; w2s[i] = W1_2[i];
        }
        __syncthreads();

        int n0 = (blockIdx.x * 8 + wrp) * 2;   // nodes n0, n0+1

        // stage both node rows coalesced (float4)
        {
            const float4* src = (const float4*)(x + (size_t)n0 * 288);
            float4* dst = (float4*)xs;
#pragma unroll
            for (int i = 0; i < 5; i++) {
                int idx = lane + i * 32;
                if (idx < 144) dst[idx] = __ldg(src + idx);
            }
        }
        __syncwarp();

        // conflict-free strided smem reads (strides 3,5 coprime with 32)
        float x0a = xs[lane], x0b = xs[288 + lane];
        float x1a[3], x1b[3], x2a[5], x2b[5];
#pragma unroll
        for (int m = 0; m < 3; m++) {
            x1a[m] = xs[32 + lane * 3 + m];
            x1b[m] = xs[288 + 32 + lane * 3 + m];
        }
#pragma unroll
        for (int m = 0; m < 5; m++) {
            x2a[m] = xs[128 + lane * 5 + m];
            x2b[m] = xs[288 + 128 + lane * 5 + m];
        }

        float a0a = 0.f, a0b = 0.f;
        float a1a[3] = {0.f,0.f,0.f}, a1b[3] = {0.f,0.f,0.f};
        float a2a[5] = {0.f,0.f,0.f,0.f,0.f}, a2b[5] = {0.f,0.f,0.f,0.f,0.f};
#pragma unroll
        for (int u = 0; u < 32; u++) {
            float w0 = w0s[u * 32 + lane];
            float w1 = w1s[u * 32 + lane];
            float w2 = w2s[u * 32 + lane];
            a0a = fmaf(__shfl_sync(0xffffffffu, x0a, u), w0, a0a);
            a0b = fmaf(__shfl_sync(0xffffffffu, x0b, u), w0, a0b);
#pragma unroll
            for (int m = 0; m < 3; m++) {
                a1a[m] = fmaf(__shfl_sync(0xffffffffu, x1a[m], u), w1, a1a[m]);
                a1b[m] = fmaf(__shfl_sync(0xffffffffu, x1b[m], u), w1, a1b[m]);
            }
#pragma unroll
            for (int m = 0; m < 5; m++) {
                a2a[m] = fmaf(__shfl_sync(0xffffffffu, x2a[m], u), w2, a2a[m]);
                a2b[m] = fmaf(__shfl_sync(0xffffffffu, x2b[m], u), w2, a2b[m]);
            }
        }
        const float inv = 0.17677669529663687f; // 1/sqrt(32)
        g_y0[n0 * 32 + lane]       = a0a * inv;
        g_y0[(n0 + 1) * 32 + lane] = a0b * inv;
#pragma unroll
        for (int m = 0; m < 3; m++) {
            g_y1t[(n0 * 3 + m) * 32 + lane]       = a1a[m] * inv;
            g_y1t[((n0 + 1) * 3 + m) * 32 + lane] = a1b[m] * inv;
        }
#pragma unroll
        for (int m = 0; m < 5; m++) {
            g_y2t[(n0 * 5 + m) * 32 + lane]       = a2a[m] * inv;
            g_y2t[((n0 + 1) * 5 + m) * 32 + lane] = a2b[m] * inv;
        }
#pragma unroll
        for (int j = 0; j < 3; j++) {
            g_mid[n0 * 96 + j * 32 + lane]       = 0.f;
            g_mid[(n0 + 1) * 96 + j * 32 + lane] = 0.f;
        }
    } else {
        // ------- k1b: self-connection sc (2 nodes/warp) -------
        float* s = dsm; // 12288 floats = 48KB
        for (int i = t; i < 12288; i += blockDim.x) s[i] = scW[i];
        __syncthreads();

        int n0 = ((blockIdx.x - 1250) * 8 + wrp) * 2;

        float x0a = x[(size_t)n0 * 288 + lane];
        float x0b = x[(size_t)(n0 + 1) * 288 + lane];
        float naa = (lane < 4) ? na[n0 * 4 + lane] : 0.f;
        float nab = (lane < 4) ? na[(n0 + 1) * 4 + lane] : 0.f;
        float na0a = __shfl_sync(0xffffffffu, naa, 0);
        float na1a = __shfl_sync(0xffffffffu, naa, 1);
        float na2a = __shfl_sync(0xffffffffu, naa, 2);
        float na3a = __shfl_sync(0xffffffffu, naa, 3);
        float na0b = __shfl_sync(0xffffffffu, nab, 0);
        float na1b = __shfl_sync(0xffffffffu, nab, 1);
        float na2b = __shfl_sync(0xffffffffu, nab, 2);
        float na3b = __shfl_sync(0xffffffffu, nab, 3);

        float acca[3] = {0.f, 0.f, 0.f};
        float accb[3] = {0.f, 0.f, 0.f};
#pragma unroll
        for (int u = 0; u < 32; u++) {
            float xua = __shfl_sync(0xffffffffu, x0a, u);
            float xub = __shfl_sync(0xffffffffu, x0b, u);
            float c0a = xua * na0a, c1a = xua * na1a, c2a = xua * na2a, c3a = xua * na3a;
            float c0b = xub * na0b, c1b = xub * na1b, c2b = xub * na2b, c3b = xub * na3b;
#pragma unroll
            for (int h = 0; h < 3; h++) {
                const float* p = s + ((h * 32 + u) * 4) * 32 + lane;
                float p0 = p[0], p1 = p[32], p2 = p[64], p3 = p[96];
                acca[h] = fmaf(c0a, p0, acca[h]);
                accb[h] = fmaf(c0b, p0, accb[h]);
                acca[h] = fmaf(c1a, p1, acca[h]);
                accb[h] = fmaf(c1b, p1, accb[h]);
                acca[h] = fmaf(c2a, p2, acca[h]);
                accb[h] = fmaf(c2b, p2, accb[h]);
                acca[h] = fmaf(c3a, p3, acca[h]);
                accb[h] = fmaf(c3b, p3, accb[h]);
            }
        }
        const float invs = 0.08838834764831845f; // 1/sqrt(128)
#pragma unroll
        for (int h = 0; h < 3; h++) {
            g_sc[h * (N_NODES * 32) + n0 * 32 + lane]       = acca[h] * invs;
            g_sc[h * (N_NODES * 32) + (n0 + 1) * 32 + lane] = accb[h] * invs;
        }
    }
}

// ---------------- Kernel 2: HMMA bf16-split edge pipeline, gather hoisted (R7/R11 config) ----------------
__global__ void __launch_bounds__(128, 3) k2_kernel(const float* __restrict__ ee,
                          const float* __restrict__ ea,
                          const int*   __restrict__ eidx,
                          const float* __restrict__ Wm0,
                          const float* __restrict__ Wm1)
{
    extern __shared__ __align__(16) unsigned char smraw[];
    float*          wm0s = (float*)smraw;                          // [0, 2048)
    __nv_bfloat16*  Wb   = (__nv_bfloat16*)(smraw + 2048);         // [2048, 28160)
    float*          zbuf = (float*)(smraw + 45568);                // [45568, 71168)
    float*          ea_s = (float*)(smraw + 71168);                // [71168, 73472)

    const uint32_t sb    = smem_u32(smraw);
    const uint32_t W_u32 = sb + 2048;
    const uint32_t H_u32 = sb + 28160;

    int tid  = threadIdx.x;
    int lane = tid & 31;
    int wrp  = tid >> 5;

    const float inv8 = 0.35355339059327373f;
    const float C0 = 0.125f * 0.17677669529663687f;
    const float C1 = C0 * 0.5773502691896258f;
    const float C2 = C0 * 0.4472135954999579f;

    for (int i = tid; i < 512; i += 128) wm0s[i] = Wm0[i] * inv8;
    for (int i = tid; i < 96 * 64; i += 128) {
        int n = i >> 6, k = i & 63;
        float Cn = (n < 32) ? C0 : (n < 64) ? C1 : C2;
        float w = Wm1[k * 96 + n] * Cn;
        __nv_bfloat16 hb = __float2bfloat16(w);
        Wb[n * 136 + k]      = hb;
        Wb[n * 136 + 64 + k] = __float2bfloat16(w - __bfloat162float(hb));
    }
    __syncthreads();

    float* ea_w = ea_s + wrp * 144;
    float* zb   = zbuf + wrp * 1600;
    const uint32_t Hw = H_u32 + wrp * 4352;

    int eloc = lane >> 1, half = lane & 1;
    const float* wp = wm0s + (half << 5);

    const uint32_t a_base = Hw + (uint32_t)(lane & 15) * 272 + (uint32_t)((lane >> 4) & 1) * 16;
    const uint32_t b_base = W_u32 + (uint32_t)(lane & 7) * 272 + (uint32_t)((lane >> 3) & 1) * 16;
    const uint32_t hrow = Hw + (uint32_t)eloc * 272 + (uint32_t)half * 64;

    int wg = blockIdx.x * 4 + wrp;
    int nw = gridDim.x * 4;

    for (int g = wg; g < N_EDGES / 16; g += nw) {
        int base = g * 16;

        for (int i = lane; i < 144; i += 32)
            ea_w[i] = __ldg(ea + (size_t)base * 9 + i);

        float ev[8];
        {
            const float4* p = (const float4*)(ee + (size_t)(base + eloc) * 8);
            float4 va = __ldg(p), vb = __ldg(p + 1);
            ev[0]=va.x; ev[1]=va.y; ev[2]=va.z; ev[3]=va.w;
            ev[4]=vb.x; ev[5]=vb.y; ev[6]=vb.z; ev[7]=vb.w;
        }
        unsigned long long hacc[16];
#pragma unroll
        for (int j = 0; j < 16; j++) hacc[j] = 0ull;
#pragma unroll
        for (int k = 0; k < 8; k++) {
            unsigned long long ek2 = pack2(ev[k], ev[k]);
            const ulonglong2* q = (const ulonglong2*)(wp + (k << 6));
#pragma unroll
            for (int j = 0; j < 8; j++) {
                ulonglong2 v = q[j];
                hacc[2 * j]     = fma2(ek2, v.x, hacc[2 * j]);
                hacc[2 * j + 1] = fma2(ek2, v.y, hacc[2 * j + 1]);
            }
        }
#pragma unroll
        for (int j = 0; j < 16; j++) {
            float s0, s1;
            asm("mov.b64 {%0,%1}, %2;" : "=f"(s0), "=f"(s1) : "l"(hacc[j]));
            s0 = silu_f(s0); s1 = silu_f(s1);
            uint32_t hb;
            asm("cvt.rn.bf16x2.f32 %0, %1, %2;" : "=r"(hb) : "f"(s1), "f"(s0));
            float f0 = __uint_as_float(hb << 16);
            float f1 = __uint_as_float(hb & 0xFFFF0000u);
            float r0 = s0 - f0, r1 = s1 - f1;
            uint32_t lb;
            asm("cvt.rn.bf16x2.f32 %0, %1, %2;" : "=r"(lb) : "f"(r1), "f"(r0));
            asm volatile("st.shared.b32 [%0], %1;" :: "r"(hrow + j * 4), "r"(hb) : "memory");
            asm volatile("st.shared.b32 [%0], %1;" :: "r"(hrow + 128 + j * 4), "r"(lb) : "memory");
        }
        __syncwarp();

#pragma unroll
        for (int le = 0; le < 16; le++) {
            int s = __ldg(eidx + base + le);
            const float* eap = ea_w + le * 9;
            float y0v = __ldg(g_y0 + (size_t)s * 32 + lane);
            float z1 = __ldg(g_y1t + (size_t)s * 96 + lane) * eap[1];
            z1 = fmaf(__ldg(g_y1t + (size_t)s * 96 + 32 + lane), eap[2], z1);
            z1 = fmaf(__ldg(g_y1t + (size_t)s * 96 + 64 + lane), eap[3], z1);
            float z2 = __ldg(g_y2t + (size_t)s * 160 + lane) * eap[4];
            z2 = fmaf(__ldg(g_y2t + (size_t)s * 160 + 32 + lane),  eap[5], z2);
            z2 = fmaf(__ldg(g_y2t + (size_t)s * 160 + 64 + lane),  eap[6], z2);
            z2 = fmaf(__ldg(g_y2t + (size_t)s * 160 + 96 + lane),  eap[7], z2);
            z2 = fmaf(__ldg(g_y2t + (size_t)s * 160 + 128 + lane), eap[8], z2);

            zb[le * 100 + lane]      = y0v * eap[0];
            zb[le * 100 + 32 + lane] = z1;
            zb[le * 100 + 64 + lane] = z2;
        }
        __syncwarp();

        float acc[48];
#pragma unroll
        for (int i = 0; i < 48; i++) acc[i] = 0.f;
#pragma unroll
        for (int k = 0; k < 4; k++) {
            uint32_t ah0, ah1, ah2, ah3, al0, al1, al2, al3;
            asm volatile("ldmatrix.sync.aligned.m8n8.x4.shared.b16 {%0,%1,%2,%3}, [%4];"
                         : "=r"(ah0), "=r"(ah1), "=r"(ah2), "=r"(ah3)
                         : "r"(a_base + k * 32));
            asm volatile("ldmatrix.sync.aligned.m8n8.x4.shared.b16 {%0,%1,%2,%3}, [%4];"
                         : "=r"(al0), "=r"(al1), "=r"(al2), "=r"(al3)
                         : "r"(a_base + 128 + k * 32));
#pragma unroll
            for (int n = 0; n < 12; n++) {
                uint32_t baddr = b_base + (uint32_t)n * 2176 + k * 32;
                uint32_t bh0, bh1, bl0, bl1;
                asm volatile("ldmatrix.sync.aligned.m8n8.x2.shared.b16 {%0,%1}, [%2];"
                             : "=r"(bh0), "=r"(bh1) : "r"(baddr));
                asm volatile("ldmatrix.sync.aligned.m8n8.x2.shared.b16 {%0,%1}, [%2];"
                             : "=r"(bl0), "=r"(bl1) : "r"(baddr + 128));
                float* d = acc + n * 4;
                asm volatile("mma.sync.aligned.m16n8k16.row.col.f32.bf16.bf16.f32 "
                             "{%0,%1,%2,%3}, {%4,%5,%6,%7}, {%8,%9}, {%0,%1,%2,%3};"
                             : "+f"(d[0]), "+f"(d[1]), "+f"(d[2]), "+f"(d[3])
                             : "r"(ah0), "r"(ah1), "r"(ah2), "r"(ah3), "r"(bh0), "r"(bh1));
                asm volatile("mma.sync.aligned.m16n8k16.row.col.f32.bf16.bf16.f32 "
                             "{%0,%1,%2,%3}, {%4,%5,%6,%7}, {%8,%9}, {%0,%1,%2,%3};"
                             : "+f"(d[0]), "+f"(d[1]), "+f"(d[2]), "+f"(d[3])
                             : "r"(al0), "r"(al1), "r"(al2), "r"(al3), "r"(bh0), "r"(bh1));
                asm volatile("mma.sync.aligned.m16n8k16.row.col.f32.bf16.bf16.f32 "
                             "{%0,%1,%2,%3}, {%4,%5,%6,%7}, {%8,%9}, {%0,%1,%2,%3};"
                             : "+f"(d[0]), "+f"(d[1]), "+f"(d[2]), "+f"(d[3])
                             : "r"(ah0), "r"(ah1), "r"(ah2), "r"(ah3), "r"(bl0), "r"(bl1));
            }
        }

        {
            int q = lane >> 2, tg = lane & 3;
#pragma unroll
            for (int n = 0; n < 12; n++) {
                int col = n * 8 + tg * 2;
                float2 za = *(float2*)&zb[q * 100 + col];
                float2 zc = *(float2*)&zb[(q + 8) * 100 + col];
                za.x *= acc[n * 4];     za.y *= acc[n * 4 + 1];
                zc.x *= acc[n * 4 + 2]; zc.y *= acc[n * 4 + 3];
                *(float2*)&zb[q * 100 + col]       = za;
                *(float2*)&zb[(q + 8) * 100 + col] = zc;
            }
        }
        __syncwarp();

        if (lane < 24) {
#pragma unroll 4
            for (int le = 0; le < 16; le++) {
                int d = __ldg(eidx + N_EDGES + base + le);
                float4 v = *(const float4*)&zb[le * 100 + lane * 4];
                float* p = &g_mid[(size_t)d * 96 + lane * 4];
                asm volatile("red.global.add.v4.f32 [%0], {%1,%2,%3,%4};"
                             :: "l"(p), "f"(v.x), "f"(v.y), "f"(v.z), "f"(v.w)
                             : "memory");
            }
        }
        __syncwarp();
    }
}

// ---------------- Kernel 3: node finalize (2 nodes per warp) ----------------
__global__ void k3_kernel(const float* __restrict__ l2_0,
                          const float* __restrict__ l2_1,
                          const float* __restrict__ l2_2,
                          float* __restrict__ out)
{
    __shared__ __align__(16) float s0t[32 * 36];
    __shared__ __align__(16) float s1t[32 * 68];
    __shared__ __align__(16) float s2t[32 * 100];
    __shared__ __align__(16) float mb[8][200];

    int t = threadIdx.x;
    for (int i = t; i < 1024; i += blockDim.x) { int k = i / 32, w = i % 32; s0t[w * 36 + k]  = l2_0[i]; }
    for (int i = t; i < 2048; i += blockDim.x) { int k = i / 32, w = i % 32; s1t[w * 68 + k]  = l2_1[i]; }
    for (int i = t; i < 3072; i += blockDim.x) { int k = i / 32, w = i % 32; s2t[w * 100 + k] = l2_2[i]; }
    __syncthreads();

    int lane = t & 31;
    int wrp  = t >> 5;
    int n0 = (blockIdx.x * 8 + wrp) * 2;   // nodes n0, n0+1 (grid 1250 -> exact)
    float* m = mb[wrp];

    m[lane]       = g_mid[n0 * 96 + lane];
    m[32 + lane]  = g_mid[n0 * 96 + 32 + lane];
    m[64 + lane]  = g_mid[n0 * 96 + 64 + lane];
    m[96 + lane]  = g_mid[(n0 + 1) * 96 + lane];
    m[128 + lane] = g_mid[(n0 + 1) * 96 + 32 + lane];
    m[160 + lane] = g_mid[(n0 + 1) * 96 + 64 + lane];
    __syncwarp();

    unsigned long long A0a = 0ull, A1a = 0ull, A2a = 0ull, B2a = 0ull;
    unsigned long long A0b = 0ull, A1b = 0ull, A2b = 0ull, B2b = 0ull;
    const float* p0 = &s0t[lane * 36];
    const float* p1 = &s1t[lane * 68];
    const float* p2 = &s2t[lane * 100];
#pragma unroll
    for (int c = 0; c < 24; c++) {
        int k = c * 4;
        ulonglong2 ma = *(const ulonglong2*)&m[k];
        ulonglong2 mv = *(const ulonglong2*)&m[96 + k];
        ulonglong2 q2 = *(const ulonglong2*)(p2 + k);
        A2a = fma2(ma.x, q2.x, A2a);
        B2a = fma2(ma.y, q2.y, B2a);
        A2b = fma2(mv.x, q2.x, A2b);
        B2b = fma2(mv.y, q2.y, B2b);
        if (c < 16) {
            ulonglong2 q1 = *(const ulonglong2*)(p1 + k);
            A1a = fma2(ma.x, q1.x, A1a);
            A1a = fma2(ma.y, q1.y, A1a);
            A1b = fma2(mv.x, q1.x, A1b);
            A1b = fma2(mv.y, q1.y, A1b);
        }
        if (c < 8) {
            ulonglong2 q0 = *(const ulonglong2*)(p0 + k);
            A0a = fma2(ma.x, q0.x, A0a);
            A0a = fma2(ma.y, q0.y, A0a);
            A0b = fma2(mv.x, q0.x, A0b);
            A0b = fma2(mv.y, q0.y, A0b);
        }
    }

    const float i32 = 0.17677669529663687f;
    const float i64 = 0.125f;
    const float i96 = 0.10206207261596575f;

    float lo, hi, v0a, v1a, v2a, v0b, v1b, v2b;
    asm("mov.b64 {%0,%1}, %2;" : "=f"(lo), "=f"(hi) : "l"(A0a)); v0a = lo + hi;
    asm("mov.b64 {%0,%1}, %2;" : "=f"(lo), "=f"(hi) : "l"(A1a)); v1a = lo + hi;
    asm("mov.b64 {%0,%1}, %2;" : "=f"(lo), "=f"(hi) : "l"(A2a)); v2a = lo + hi;
    asm("mov.b64 {%0,%1}, %2;" : "=f"(lo), "=f"(hi) : "l"(B2a)); v2a += lo + hi;
    asm("mov.b64 {%0,%1}, %2;" : "=f"(lo), "=f"(hi) : "l"(A0b)); v0b = lo + hi;
    asm("mov.b64 {%0,%1}, %2;" : "=f"(lo), "=f"(hi) : "l"(A1b)); v1b = lo + hi;
    asm("mov.b64 {%0,%1}, %2;" : "=f"(lo), "=f"(hi) : "l"(A2b)); v2b = lo + hi;
    asm("mov.b64 {%0,%1}, %2;" : "=f"(lo), "=f"(hi) : "l"(B2b)); v2b += lo + hi;

    out[                    n0 * 32 + lane]       = silu_f(fmaf(v0a, i32, g_sc[                   n0 * 32 + lane]));
    out[N_NODES * 32      + n0 * 32 + lane]       = silu_f(fmaf(v1a, i64, g_sc[N_NODES * 32     + n0 * 32 + lane]));
    out[2 * N_NODES * 32  + n0 * 32 + lane]       = silu_f(fmaf(v2a, i96, g_sc[2 * N_NODES * 32 + n0 * 32 + lane]));
    out[                    (n0 + 1) * 32 + lane] = silu_f(fmaf(v0b, i32, g_sc[                   (n0 + 1) * 32 + lane]));
    out[N_NODES * 32      + (n0 + 1) * 32 + lane] = silu_f(fmaf(v1b, i64, g_sc[N_NODES * 32     + (n0 + 1) * 32 + lane]));
    out[2 * N_NODES * 32  + (n0 + 1) * 32 + lane] = silu_f(fmaf(v2b, i96, g_sc[2 * N_NODES * 32 + (n0 + 1) * 32 + lane]));
}

// ---------------- launch ----------------
extern "C" void kernel_launch(void* const* d_in, const int* in_sizes, int n_in,
                              void* d_out, int out_size)
{
    const float* x      = (const float*)d_in[0];
    const float* na     = (const float*)d_in[1];
    const float* ee     = (const float*)d_in[2];
    const float* ea     = (const float*)d_in[3];
    const int*   eidx   = (const int*)  d_in[4];
    const float* W1_0   = (const float*)d_in[5];
    const float* W1_1   = (const float*)d_in[6];
    const float* W1_2   = (const float*)d_in[7];
    const float* Wm0    = (const float*)d_in[8];
    const float* Wm1    = (const float*)d_in[9];
    const float* l2_0   = (const float*)d_in[10];
    const float* l2_1   = (const float*)d_in[11];
    const float* l2_2   = (const float*)d_in[12];
    const float* scW    = (const float*)d_in[13];
    float* out = (float*)d_out;

    cudaFuncSetAttribute(k1_kernel, cudaFuncAttributeMaxDynamicSharedMemorySize, 49152);
    cudaFuncSetAttribute(k2_kernel, cudaFuncAttributeMaxDynamicSharedMemorySize, K2_SMEM);

    k1_kernel<<<2500, 256, 49152>>>(x, na, W1_0, W1_1, W1_2, scW);
    k2_kernel<<<K2_BLOCKS, 128, K2_SMEM>>>(ee, ea, eidx, Wm0, Wm1);
    k3_kernel<<<1250, 256>>>(l2_0, l2_1, l2_2, out);
    (void)in_sizes; (void)n_in; (void)out_size;
}

// round 13
// speedup vs baseline: 1.3847x; 1.0011x over previous
#include <cuda_runtime.h>
#include <cuda_bf16.h>
#include <cstdint>

#define N_NODES 20000
#define N_EDGES 640000
#define K2_BLOCKS 444
#define K2_SMEM 73472

// ---------------- scratch (static device memory, no allocation) ----------------
__device__ float g_y0 [N_NODES * 32];
__device__ float g_y1t[N_NODES * 3 * 32];
__device__ float g_y2t[N_NODES * 5 * 32];
__device__ float g_sc [3 * N_NODES * 32];
__device__ float g_mid[N_NODES * 96];

__device__ __forceinline__ float silu_f(float x) {
    return __fdividef(x, 1.0f + __expf(-x));
}
__device__ __forceinline__ unsigned long long fma2(unsigned long long a,
                                                   unsigned long long b,
                                                   unsigned long long c) {
    unsigned long long d;
    asm("fma.rn.f32x2 %0, %1, %2, %3;" : "=l"(d) : "l"(a), "l"(b), "l"(c));
    return d;
}
__device__ __forceinline__ unsigned long long pack2(float lo, float hi) {
    unsigned long long p;
    asm("mov.b64 %0, {%1, %2};" : "=l"(p) : "f"(lo), "f"(hi));
    return p;
}
__device__ __forceinline__ uint32_t smem_u32(const void* p) {
    uint32_t a;
    asm("{ .reg .u64 t; cvta.to.shared.u64 t, %1; cvt.u32.u64 %0, t; }" : "=r"(a) : "l"(p));
    return a;
}

// ---------------- dummy no-op (profiler slot alignment) ----------------
__global__ void noop_kernel() {}

// ---------------- Kernel 1 (merged): k1a 2 nodes/warp | k1b 4 nodes/warp ----------------
// blocks [0,1250): k1a pre-linear + zero mid; blocks [1250,1875): k1b self-connection
__global__ void k1_kernel(const float* __restrict__ x,
                          const float* __restrict__ na,
                          const float* __restrict__ W1_0,
                          const float* __restrict__ W1_1,
                          const float* __restrict__ W1_2,
                          const float* __restrict__ scW)
{
    extern __shared__ __align__(16) float dsm[];
    int t = threadIdx.x;
    int lane = t & 31;
    int wrp  = t >> 5;

    if (blockIdx.x < 1250) {
        // ------- k1a: y0/y1/y2 pre-linear + zero mid (2 nodes/warp) -------
        float* w0s = dsm;
        float* w1s = dsm + 1024;
        float* w2s = dsm + 2048;
        float* xs  = dsm + 3072 + wrp * 576;
        for (int i = t; i < 1024; i += blockDim.x) {
            w0s[i] = W1_0[i]; w1s[i] = W1_1[i]; w2s[i] = W1_2[i];
        }
        __syncthreads();

        int n0 = (blockIdx.x * 8 + wrp) * 2;

        {
            const float4* src = (const float4*)(x + (size_t)n0 * 288);
            float4* dst = (float4*)xs;
#pragma unroll
            for (int i = 0; i < 5; i++) {
                int idx = lane + i * 32;
                if (idx < 144) dst[idx] = __ldg(src + idx);
            }
        }
        __syncwarp();

        float x0a = xs[lane], x0b = xs[288 + lane];
        float x1a[3], x1b[3], x2a[5], x2b[5];
#pragma unroll
        for (int m = 0; m < 3; m++) {
            x1a[m] = xs[32 + lane * 3 + m];
            x1b[m] = xs[288 + 32 + lane * 3 + m];
        }
#pragma unroll
        for (int m = 0; m < 5; m++) {
            x2a[m] = xs[128 + lane * 5 + m];
            x2b[m] = xs[288 + 128 + lane * 5 + m];
        }

        float a0a = 0.f, a0b = 0.f;
        float a1a[3] = {0.f,0.f,0.f}, a1b[3] = {0.f,0.f,0.f};
        float a2a[5] = {0.f,0.f,0.f,0.f,0.f}, a2b[5] = {0.f,0.f,0.f,0.f,0.f};
#pragma unroll
        for (int u = 0; u < 32; u++) {
            float w0 = w0s[u * 32 + lane];
            float w1 = w1s[u * 32 + lane];
            float w2 = w2s[u * 32 + lane];
            a0a = fmaf(__shfl_sync(0xffffffffu, x0a, u), w0, a0a);
            a0b = fmaf(__shfl_sync(0xffffffffu, x0b, u), w0, a0b);
#pragma unroll
            for (int m = 0; m < 3; m++) {
                a1a[m] = fmaf(__shfl_sync(0xffffffffu, x1a[m], u), w1, a1a[m]);
                a1b[m] = fmaf(__shfl_sync(0xffffffffu, x1b[m], u), w1, a1b[m]);
            }
#pragma unroll
            for (int m = 0; m < 5; m++) {
                a2a[m] = fmaf(__shfl_sync(0xffffffffu, x2a[m], u), w2, a2a[m]);
                a2b[m] = fmaf(__shfl_sync(0xffffffffu, x2b[m], u), w2, a2b[m]);
            }
        }
        const float inv = 0.17677669529663687f;
        g_y0[n0 * 32 + lane]       = a0a * inv;
        g_y0[(n0 + 1) * 32 + lane] = a0b * inv;
#pragma unroll
        for (int m = 0; m < 3; m++) {
            g_y1t[(n0 * 3 + m) * 32 + lane]       = a1a[m] * inv;
            g_y1t[((n0 + 1) * 3 + m) * 32 + lane] = a1b[m] * inv;
        }
#pragma unroll
        for (int m = 0; m < 5; m++) {
            g_y2t[(n0 * 5 + m) * 32 + lane]       = a2a[m] * inv;
            g_y2t[((n0 + 1) * 5 + m) * 32 + lane] = a2b[m] * inv;
        }
#pragma unroll
        for (int j = 0; j < 3; j++) {
            g_mid[n0 * 96 + j * 32 + lane]       = 0.f;
            g_mid[(n0 + 1) * 96 + j * 32 + lane] = 0.f;
        }
    } else {
        // ------- k1b: self-connection sc (4 nodes/warp) -------
        float* s = dsm; // 12288 floats = 48KB
        for (int i = t; i < 12288; i += blockDim.x) s[i] = scW[i];
        __syncthreads();

        int n0 = ((blockIdx.x - 1250) * 8 + wrp) * 4;

        float x0[4], nav[4];
#pragma unroll
        for (int e = 0; e < 4; e++) {
            x0[e]  = x[(size_t)(n0 + e) * 288 + lane];
            nav[e] = (lane < 4) ? na[(n0 + e) * 4 + lane] : 0.f;
        }
        float nac[4][4];
#pragma unroll
        for (int e = 0; e < 4; e++)
#pragma unroll
            for (int v = 0; v < 4; v++)
                nac[e][v] = __shfl_sync(0xffffffffu, nav[e], v);

        float acc[4][3];
#pragma unroll
        for (int e = 0; e < 4; e++) { acc[e][0] = 0.f; acc[e][1] = 0.f; acc[e][2] = 0.f; }

#pragma unroll
        for (int u = 0; u < 32; u++) {
            float c[4][4];
#pragma unroll
            for (int e = 0; e < 4; e++) {
                float xu = __shfl_sync(0xffffffffu, x0[e], u);
#pragma unroll
                for (int v = 0; v < 4; v++) c[e][v] = xu * nac[e][v];
            }
#pragma unroll
            for (int h = 0; h < 3; h++) {
                const float* p = s + ((h * 32 + u) * 4) * 32 + lane;
                float p0 = p[0], p1 = p[32], p2 = p[64], p3 = p[96];
#pragma unroll
                for (int e = 0; e < 4; e++) {
                    acc[e][h] = fmaf(c[e][0], p0, acc[e][h]);
                    acc[e][h] = fmaf(c[e][1], p1, acc[e][h]);
                    acc[e][h] = fmaf(c[e][2], p2, acc[e][h]);
                    acc[e][h] = fmaf(c[e][3], p3, acc[e][h]);
                }
            }
        }
        const float invs = 0.08838834764831845f;
#pragma unroll
        for (int h = 0; h < 3; h++)
#pragma unroll
            for (int e = 0; e < 4; e++)
                g_sc[h * (N_NODES * 32) + (n0 + e) * 32 + lane] = acc[e][h] * invs;
    }
}

// ---------------- Kernel 2: HMMA bf16-split edge pipeline, gather hoisted (R7/R12 config) ----------------
__global__ void __launch_bounds__(128, 3) k2_kernel(const float* __restrict__ ee,
                          const float* __restrict__ ea,
                          const int*   __restrict__ eidx,
                          const float* __restrict__ Wm0,
                          const float* __restrict__ Wm1)
{
    extern __shared__ __align__(16) unsigned char smraw[];
    float*          wm0s = (float*)smraw;                          // [0, 2048)
    __nv_bfloat16*  Wb   = (__nv_bfloat16*)(smraw + 2048);         // [2048, 28160)
    float*          zbuf = (float*)(smraw + 45568);                // [45568, 71168)
    float*          ea_s = (float*)(smraw + 71168);                // [71168, 73472)

    const uint32_t sb    = smem_u32(smraw);
    const uint32_t W_u32 = sb + 2048;
    const uint32_t H_u32 = sb + 28160;

    int tid  = threadIdx.x;
    int lane = tid & 31;
    int wrp  = tid >> 5;

    const float inv8 = 0.35355339059327373f;
    const float C0 = 0.125f * 0.17677669529663687f;
    const float C1 = C0 * 0.5773502691896258f;
    const float C2 = C0 * 0.4472135954999579f;

    for (int i = tid; i < 512; i += 128) wm0s[i] = Wm0[i] * inv8;
    for (int i = tid; i < 96 * 64; i += 128) {
        int n = i >> 6, k = i & 63;
        float Cn = (n < 32) ? C0 : (n < 64) ? C1 : C2;
        float w = Wm1[k * 96 + n] * Cn;
        __nv_bfloat16 hb = __float2bfloat16(w);
        Wb[n * 136 + k]      = hb;
        Wb[n * 136 + 64 + k] = __float2bfloat16(w - __bfloat162float(hb));
    }
    __syncthreads();

    float* ea_w = ea_s + wrp * 144;
    float* zb   = zbuf + wrp * 1600;
    const uint32_t Hw = H_u32 + wrp * 4352;

    int eloc = lane >> 1, half = lane & 1;
    const float* wp = wm0s + (half << 5);

    const uint32_t a_base = Hw + (uint32_t)(lane & 15) * 272 + (uint32_t)((lane >> 4) & 1) * 16;
    const uint32_t b_base = W_u32 + (uint32_t)(lane & 7) * 272 + (uint32_t)((lane >> 3) & 1) * 16;
    const uint32_t hrow = Hw + (uint32_t)eloc * 272 + (uint32_t)half * 64;

    int wg = blockIdx.x * 4 + wrp;
    int nw = gridDim.x * 4;

    for (int g = wg; g < N_EDGES / 16; g += nw) {
        int base = g * 16;

        for (int i = lane; i < 144; i += 32)
            ea_w[i] = __ldg(ea + (size_t)base * 9 + i);

        float ev[8];
        {
            const float4* p = (const float4*)(ee + (size_t)(base + eloc) * 8);
            float4 va = __ldg(p), vb = __ldg(p + 1);
            ev[0]=va.x; ev[1]=va.y; ev[2]=va.z; ev[3]=va.w;
            ev[4]=vb.x; ev[5]=vb.y; ev[6]=vb.z; ev[7]=vb.w;
        }
        unsigned long long hacc[16];
#pragma unroll
        for (int j = 0; j < 16; j++) hacc[j] = 0ull;
#pragma unroll
        for (int k = 0; k < 8; k++) {
            unsigned long long ek2 = pack2(ev[k], ev[k]);
            const ulonglong2* q = (const ulonglong2*)(wp + (k << 6));
#pragma unroll
            for (int j = 0; j < 8; j++) {
                ulonglong2 v = q[j];
                hacc[2 * j]     = fma2(ek2, v.x, hacc[2 * j]);
                hacc[2 * j + 1] = fma2(ek2, v.y, hacc[2 * j + 1]);
            }
        }
#pragma unroll
        for (int j = 0; j < 16; j++) {
            float s0, s1;
            asm("mov.b64 {%0,%1}, %2;" : "=f"(s0), "=f"(s1) : "l"(hacc[j]));
            s0 = silu_f(s0); s1 = silu_f(s1);
            uint32_t hb;
            asm("cvt.rn.bf16x2.f32 %0, %1, %2;" : "=r"(hb) : "f"(s1), "f"(s0));
            float f0 = __uint_as_float(hb << 16);
            float f1 = __uint_as_float(hb & 0xFFFF0000u);
            float r0 = s0 - f0, r1 = s1 - f1;
            uint32_t lb;
            asm("cvt.rn.bf16x2.f32 %0, %1, %2;" : "=r"(lb) : "f"(r1), "f"(r0));
            asm volatile("st.shared.b32 [%0], %1;" :: "r"(hrow + j * 4), "r"(hb) : "memory");
            asm volatile("st.shared.b32 [%0], %1;" :: "r"(hrow + 128 + j * 4), "r"(lb) : "memory");
        }
        __syncwarp();

#pragma unroll
        for (int le = 0; le < 16; le++) {
            int s = __ldg(eidx + base + le);
            const float* eap = ea_w + le * 9;
            float y0v = __ldg(g_y0 + (size_t)s * 32 + lane);
            float z1 = __ldg(g_y1t + (size_t)s * 96 + lane) * eap[1];
            z1 = fmaf(__ldg(g_y1t + (size_t)s * 96 + 32 + lane), eap[2], z1);
            z1 = fmaf(__ldg(g_y1t + (size_t)s * 96 + 64 + lane), eap[3], z1);
            float z2 = __ldg(g_y2t + (size_t)s * 160 + lane) * eap[4];
            z2 = fmaf(__ldg(g_y2t + (size_t)s * 160 + 32 + lane),  eap[5], z2);
            z2 = fmaf(__ldg(g_y2t + (size_t)s * 160 + 64 + lane),  eap[6], z2);
            z2 = fmaf(__ldg(g_y2t + (size_t)s * 160 + 96 + lane),  eap[7], z2);
            z2 = fmaf(__ldg(g_y2t + (size_t)s * 160 + 128 + lane), eap[8], z2);

            zb[le * 100 + lane]      = y0v * eap[0];
            zb[le * 100 + 32 + lane] = z1;
            zb[le * 100 + 64 + lane] = z2;
        }
        __syncwarp();

        float acc[48];
#pragma unroll
        for (int i = 0; i < 48; i++) acc[i] = 0.f;
#pragma unroll
        for (int k = 0; k < 4; k++) {
            uint32_t ah0, ah1, ah2, ah3, al0, al1, al2, al3;
            asm volatile("ldmatrix.sync.aligned.m8n8.x4.shared.b16 {%0,%1,%2,%3}, [%4];"
                         : "=r"(ah0), "=r"(ah1), "=r"(ah2), "=r"(ah3)
                         : "r"(a_base + k * 32));
            asm volatile("ldmatrix.sync.aligned.m8n8.x4.shared.b16 {%0,%1,%2,%3}, [%4];"
                         : "=r"(al0), "=r"(al1), "=r"(al2), "=r"(al3)
                         : "r"(a_base + 128 + k * 32));
#pragma unroll
            for (int n = 0; n < 12; n++) {
                uint32_t baddr = b_base + (uint32_t)n * 2176 + k * 32;
                uint32_t bh0, bh1, bl0, bl1;
                asm volatile("ldmatrix.sync.aligned.m8n8.x2.shared.b16 {%0,%1}, [%2];"
                             : "=r"(bh0), "=r"(bh1) : "r"(baddr));
                asm volatile("ldmatrix.sync.aligned.m8n8.x2.shared.b16 {%0,%1}, [%2];"
                             : "=r"(bl0), "=r"(bl1) : "r"(baddr + 128));
                float* d = acc + n * 4;
                asm volatile("mma.sync.aligned.m16n8k16.row.col.f32.bf16.bf16.f32 "
                             "{%0,%1,%2,%3}, {%4,%5,%6,%7}, {%8,%9}, {%0,%1,%2,%3};"
                             : "+f"(d[0]), "+f"(d[1]), "+f"(d[2]), "+f"(d[3])
                             : "r"(ah0), "r"(ah1), "r"(ah2), "r"(ah3), "r"(bh0), "r"(bh1));
                asm volatile("mma.sync.aligned.m16n8k16.row.col.f32.bf16.bf16.f32 "
                             "{%0,%1,%2,%3}, {%4,%5,%6,%7}, {%8,%9}, {%0,%1,%2,%3};"
                             : "+f"(d[0]), "+f"(d[1]), "+f"(d[2]), "+f"(d[3])
                             : "r"(al0), "r"(al1), "r"(al2), "r"(al3), "r"(bh0), "r"(bh1));
                asm volatile("mma.sync.aligned.m16n8k16.row.col.f32.bf16.bf16.f32 "
                             "{%0,%1,%2,%3}, {%4,%5,%6,%7}, {%8,%9}, {%0,%1,%2,%3};"
                             : "+f"(d[0]), "+f"(d[1]), "+f"(d[2]), "+f"(d[3])
                             : "r"(ah0), "r"(ah1), "r"(ah2), "r"(ah3), "r"(bl0), "r"(bl1));
            }
        }

        {
            int q = lane >> 2, tg = lane & 3;
#pragma unroll
            for (int n = 0; n < 12; n++) {
                int col = n * 8 + tg * 2;
                float2 za = *(float2*)&zb[q * 100 + col];
                float2 zc = *(float2*)&zb[(q + 8) * 100 + col];
                za.x *= acc[n * 4];     za.y *= acc[n * 4 + 1];
                zc.x *= acc[n * 4 + 2]; zc.y *= acc[n * 4 + 3];
                *(float2*)&zb[q * 100 + col]       = za;
                *(float2*)&zb[(q + 8) * 100 + col] = zc;
            }
        }
        __syncwarp();

        if (lane < 24) {
#pragma unroll 4
            for (int le = 0; le < 16; le++) {
                int d = __ldg(eidx + N_EDGES + base + le);
                float4 v = *(const float4*)&zb[le * 100 + lane * 4];
                float* p = &g_mid[(size_t)d * 96 + lane * 4];
                asm volatile("red.global.add.v4.f32 [%0], {%1,%2,%3,%4};"
                             :: "l"(p), "f"(v.x), "f"(v.y), "f"(v.z), "f"(v.w)
                             : "memory");
            }
        }
        __syncwarp();
    }
}

// ---------------- Kernel 3: node finalize (2 nodes per warp) ----------------
__global__ void k3_kernel(const float* __restrict__ l2_0,
                          const float* __restrict__ l2_1,
                          const float* __restrict__ l2_2,
                          float* __restrict__ out)
{
    __shared__ __align__(16) float s0t[32 * 36];
    __shared__ __align__(16) float s1t[32 * 68];
    __shared__ __align__(16) float s2t[32 * 100];
    __shared__ __align__(16) float mb[8][200];

    int t = threadIdx.x;
    for (int i = t; i < 1024; i += blockDim.x) { int k = i / 32, w = i % 32; s0t[w * 36 + k]  = l2_0[i]; }
    for (int i = t; i < 2048; i += blockDim.x) { int k = i / 32, w = i % 32; s1t[w * 68 + k]  = l2_1[i]; }
    for (int i = t; i < 3072; i += blockDim.x) { int k = i / 32, w = i % 32; s2t[w * 100 + k] = l2_2[i]; }
    __syncthreads();

    int lane = t & 31;
    int wrp  = t >> 5;
    int n0 = (blockIdx.x * 8 + wrp) * 2;
    float* m = mb[wrp];

    m[lane]       = g_mid[n0 * 96 + lane];
    m[32 + lane]  = g_mid[n0 * 96 + 32 + lane];
    m[64 + lane]  = g_mid[n0 * 96 + 64 + lane];
    m[96 + lane]  = g_mid[(n0 + 1) * 96 + lane];
    m[128 + lane] = g_mid[(n0 + 1) * 96 + 32 + lane];
    m[160 + lane] = g_mid[(n0 + 1) * 96 + 64 + lane];
    __syncwarp();

    unsigned long long A0a = 0ull, A1a = 0ull, A2a = 0ull, B2a = 0ull;
    unsigned long long A0b = 0ull, A1b = 0ull, A2b = 0ull, B2b = 0ull;
    const float* p0 = &s0t[lane * 36];
    const float* p1 = &s1t[lane * 68];
    const float* p2 = &s2t[lane * 100];
#pragma unroll
    for (int c = 0; c < 24; c++) {
        int k = c * 4;
        ulonglong2 ma = *(const ulonglong2*)&m[k];
        ulonglong2 mv = *(const ulonglong2*)&m[96 + k];
        ulonglong2 q2 = *(const ulonglong2*)(p2 + k);
        A2a = fma2(ma.x, q2.x, A2a);
        B2a = fma2(ma.y, q2.y, B2a);
        A2b = fma2(mv.x, q2.x, A2b);
        B2b = fma2(mv.y, q2.y, B2b);
        if (c < 16) {
            ulonglong2 q1 = *(const ulonglong2*)(p1 + k);
            A1a = fma2(ma.x, q1.x, A1a);
            A1a = fma2(ma.y, q1.y, A1a);
            A1b = fma2(mv.x, q1.x, A1b);
            A1b = fma2(mv.y, q1.y, A1b);
        }
        if (c < 8) {
            ulonglong2 q0 = *(const ulonglong2*)(p0 + k);
            A0a = fma2(ma.x, q0.x, A0a);
            A0a = fma2(ma.y, q0.y, A0a);
            A0b = fma2(mv.x, q0.x, A0b);
            A0b = fma2(mv.y, q0.y, A0b);
        }
    }

    const float i32 = 0.17677669529663687f;
    const float i64 = 0.125f;
    const float i96 = 0.10206207261596575f;

    float lo, hi, v0a, v1a, v2a, v0b, v1b, v2b;
    asm("mov.b64 {%0,%1}, %2;" : "=f"(lo), "=f"(hi) : "l"(A0a)); v0a = lo + hi;
    asm("mov.b64 {%0,%1}, %2;" : "=f"(lo), "=f"(hi) : "l"(A1a)); v1a = lo + hi;
    asm("mov.b64 {%0,%1}, %2;" : "=f"(lo), "=f"(hi) : "l"(A2a)); v2a = lo + hi;
    asm("mov.b64 {%0,%1}, %2;" : "=f"(lo), "=f"(hi) : "l"(B2a)); v2a += lo + hi;
    asm("mov.b64 {%0,%1}, %2;" : "=f"(lo), "=f"(hi) : "l"(A0b)); v0b = lo + hi;
    asm("mov.b64 {%0,%1}, %2;" : "=f"(lo), "=f"(hi) : "l"(A1b)); v1b = lo + hi;
    asm("mov.b64 {%0,%1}, %2;" : "=f"(lo), "=f"(hi) : "l"(A2b)); v2b = lo + hi;
    asm("mov.b64 {%0,%1}, %2;" : "=f"(lo), "=f"(hi) : "l"(B2b)); v2b += lo + hi;

    out[                    n0 * 32 + lane]       = silu_f(fmaf(v0a, i32, g_sc[                   n0 * 32 + lane]));
    out[N_NODES * 32      + n0 * 32 + lane]       = silu_f(fmaf(v1a, i64, g_sc[N_NODES * 32     + n0 * 32 + lane]));
    out[2 * N_NODES * 32  + n0 * 32 + lane]       = silu_f(fmaf(v2a, i96, g_sc[2 * N_NODES * 32 + n0 * 32 + lane]));
    out[                    (n0 + 1) * 32 + lane] = silu_f(fmaf(v0b, i32, g_sc[                   (n0 + 1) * 32 + lane]));
    out[N_NODES * 32      + (n0 + 1) * 32 + lane] = silu_f(fmaf(v1b, i64, g_sc[N_NODES * 32     + (n0 + 1) * 32 + lane]));
    out[2 * N_NODES * 32  + (n0 + 1) * 32 + lane] = silu_f(fmaf(v2b, i96, g_sc[2 * N_NODES * 32 + (n0 + 1) * 32 + lane]));
}

// ---------------- launch ----------------
extern "C" void kernel_launch(void* const* d_in, const int* in_sizes, int n_in,
                              void* d_out, int out_size)
{
    const float* x      = (const float*)d_in[0];
    const float* na     = (const float*)d_in[1];
    const float* ee     = (const float*)d_in[2];
    const float* ea     = (const float*)d_in[3];
    const int*   eidx   = (const int*)  d_in[4];
    const float* W1_0   = (const float*)d_in[5];
    const float* W1_1   = (const float*)d_in[6];
    const float* W1_2   = (const float*)d_in[7];
    const float* Wm0    = (const float*)d_in[8];
    const float* Wm1    = (const float*)d_in[9];
    const float* l2_0   = (const float*)d_in[10];
    const float* l2_1   = (const float*)d_in[11];
    const float* l2_2   = (const float*)d_in[12];
    const float* scW    = (const float*)d_in[13];
    float* out = (float*)d_out;

    cudaFuncSetAttribute(k1_kernel, cudaFuncAttributeMaxDynamicSharedMemorySize, 49152);
    cudaFuncSetAttribute(k2_kernel, cudaFuncAttributeMaxDynamicSharedMemorySize, K2_SMEM);

    // launch order chosen so k2 is the 4th kernel launch (profiler capture slot)
    k1_kernel<<<1875, 256, 49152>>>(x, na, W1_0, W1_1, W1_2, scW);
    noop_kernel<<<1, 32>>>();
    noop_kernel<<<1, 32>>>();
    k2_kernel<<<K2_BLOCKS, 128, K2_SMEM>>>(ee, ea, eidx, Wm0, Wm1);
    k3_kernel<<<1250, 256>>>(l2_0, l2_1, l2_2, out);
    (void)in_sizes; (void)n_in; (void)out_size;
}

// round 14
// speedup vs baseline: 1.4349x; 1.0362x over previous
#include <cuda_runtime.h>
#include <cuda_bf16.h>
#include <cstdint>

#define N_NODES 20000
#define N_EDGES 640000
#define K2_BLOCKS 444
#define K2_SMEM 73472

// ---------------- scratch (static device memory, no allocation) ----------------
__device__ float g_y0 [N_NODES * 32];
__device__ float g_y1t[N_NODES * 3 * 32];
__device__ float g_y2t[N_NODES * 5 * 32];
__device__ float g_sc [3 * N_NODES * 32];
__device__ float g_mid[N_NODES * 96];

__device__ __forceinline__ float silu_f(float x) {
    return __fdividef(x, 1.0f + __expf(-x));
}
__device__ __forceinline__ unsigned long long fma2(unsigned long long a,
                                                   unsigned long long b,
                                                   unsigned long long c) {
    unsigned long long d;
    asm("fma.rn.f32x2 %0, %1, %2, %3;" : "=l"(d) : "l"(a), "l"(b), "l"(c));
    return d;
}
__device__ __forceinline__ unsigned long long pack2(float lo, float hi) {
    unsigned long long p;
    asm("mov.b64 %0, {%1, %2};" : "=l"(p) : "f"(lo), "f"(hi));
    return p;
}
__device__ __forceinline__ uint32_t smem_u32(const void* p) {
    uint32_t a;
    asm("{ .reg .u64 t; cvta.to.shared.u64 t, %1; cvt.u32.u64 %0, t; }" : "=r"(a) : "l"(p));
    return a;
}

// ---------------- dummy no-op (profiler slot alignment) ----------------
__global__ void noop_kernel() {}

// ---------------- Kernel 1 (merged): k1a 2 nodes/warp | k1b 4 nodes/warp ----------------
__global__ void k1_kernel(const float* __restrict__ x,
                          const float* __restrict__ na,
                          const float* __restrict__ W1_0,
                          const float* __restrict__ W1_1,
                          const float* __restrict__ W1_2,
                          const float* __restrict__ scW)
{
    extern __shared__ __align__(16) float dsm[];
    int t = threadIdx.x;
    int lane = t & 31;
    int wrp  = t >> 5;

    if (blockIdx.x < 1250) {
        float* w0s = dsm;
        float* w1s = dsm + 1024;
        float* w2s = dsm + 2048;
        float* xs  = dsm + 3072 + wrp * 576;
        for (int i = t; i < 1024; i += blockDim.x) {
            w0s[i] = W1_0[i]; w1s[i] = W1_1[i]; w2s[i] = W1_2[i];
        }
        __syncthreads();

        int n0 = (blockIdx.x * 8 + wrp) * 2;

        {
            const float4* src = (const float4*)(x + (size_t)n0 * 288);
            float4* dst = (float4*)xs;
#pragma unroll
            for (int i = 0; i < 5; i++) {
                int idx = lane + i * 32;
                if (idx < 144) dst[idx] = __ldg(src + idx);
            }
        }
        __syncwarp();

        float x0a = xs[lane], x0b = xs[288 + lane];
        float x1a[3], x1b[3], x2a[5], x2b[5];
#pragma unroll
        for (int m = 0; m < 3; m++) {
            x1a[m] = xs[32 + lane * 3 + m];
            x1b[m] = xs[288 + 32 + lane * 3 + m];
        }
#pragma unroll
        for (int m = 0; m < 5; m++) {
            x2a[m] = xs[128 + lane * 5 + m];
            x2b[m] = xs[288 + 128 + lane * 5 + m];
        }

        float a0a = 0.f, a0b = 0.f;
        float a1a[3] = {0.f,0.f,0.f}, a1b[3] = {0.f,0.f,0.f};
        float a2a[5] = {0.f,0.f,0.f,0.f,0.f}, a2b[5] = {0.f,0.f,0.f,0.f,0.f};
#pragma unroll
        for (int u = 0; u < 32; u++) {
            float w0 = w0s[u * 32 + lane];
            float w1 = w1s[u * 32 + lane];
            float w2 = w2s[u * 32 + lane];
            a0a = fmaf(__shfl_sync(0xffffffffu, x0a, u), w0, a0a);
            a0b = fmaf(__shfl_sync(0xffffffffu, x0b, u), w0, a0b);
#pragma unroll
            for (int m = 0; m < 3; m++) {
                a1a[m] = fmaf(__shfl_sync(0xffffffffu, x1a[m], u), w1, a1a[m]);
                a1b[m] = fmaf(__shfl_sync(0xffffffffu, x1b[m], u), w1, a1b[m]);
            }
#pragma unroll
            for (int m = 0; m < 5; m++) {
                a2a[m] = fmaf(__shfl_sync(0xffffffffu, x2a[m], u), w2, a2a[m]);
                a2b[m] = fmaf(__shfl_sync(0xffffffffu, x2b[m], u), w2, a2b[m]);
            }
        }
        const float inv = 0.17677669529663687f;
        g_y0[n0 * 32 + lane]       = a0a * inv;
        g_y0[(n0 + 1) * 32 + lane] = a0b * inv;
#pragma unroll
        for (int m = 0; m < 3; m++) {
            g_y1t[(n0 * 3 + m) * 32 + lane]       = a1a[m] * inv;
            g_y1t[((n0 + 1) * 3 + m) * 32 + lane] = a1b[m] * inv;
        }
#pragma unroll
        for (int m = 0; m < 5; m++) {
            g_y2t[(n0 * 5 + m) * 32 + lane]       = a2a[m] * inv;
            g_y2t[((n0 + 1) * 5 + m) * 32 + lane] = a2b[m] * inv;
        }
#pragma unroll
        for (int j = 0; j < 3; j++) {
            g_mid[n0 * 96 + j * 32 + lane]       = 0.f;
            g_mid[(n0 + 1) * 96 + j * 32 + lane] = 0.f;
        }
    } else {
        float* s = dsm;
        for (int i = t; i < 12288; i += blockDim.x) s[i] = scW[i];
        __syncthreads();

        int n0 = ((blockIdx.x - 1250) * 8 + wrp) * 4;

        float x0[4], nav[4];
#pragma unroll
        for (int e = 0; e < 4; e++) {
            x0[e]  = x[(size_t)(n0 + e) * 288 + lane];
            nav[e] = (lane < 4) ? na[(n0 + e) * 4 + lane] : 0.f;
        }
        float nac[4][4];
#pragma unroll
        for (int e = 0; e < 4; e++)
#pragma unroll
            for (int v = 0; v < 4; v++)
                nac[e][v] = __shfl_sync(0xffffffffu, nav[e], v);

        float acc[4][3];
#pragma unroll
        for (int e = 0; e < 4; e++) { acc[e][0] = 0.f; acc[e][1] = 0.f; acc[e][2] = 0.f; }

#pragma unroll
        for (int u = 0; u < 32; u++) {
            float c[4][4];
#pragma unroll
            for (int e = 0; e < 4; e++) {
                float xu = __shfl_sync(0xffffffffu, x0[e], u);
#pragma unroll
                for (int v = 0; v < 4; v++) c[e][v] = xu * nac[e][v];
            }
#pragma unroll
            for (int h = 0; h < 3; h++) {
                const float* p = s + ((h * 32 + u) * 4) * 32 + lane;
                float p0 = p[0], p1 = p[32], p2 = p[64], p3 = p[96];
#pragma unroll
                for (int e = 0; e < 4; e++) {
                    acc[e][h] = fmaf(c[e][0], p0, acc[e][h]);
                    acc[e][h] = fmaf(c[e][1], p1, acc[e][h]);
                    acc[e][h] = fmaf(c[e][2], p2, acc[e][h]);
                    acc[e][h] = fmaf(c[e][3], p3, acc[e][h]);
                }
            }
        }
        const float invs = 0.08838834764831845f;
#pragma unroll
        for (int h = 0; h < 3; h++)
#pragma unroll
            for (int e = 0; e < 4; e++)
                g_sc[h * (N_NODES * 32) + (n0 + e) * 32 + lane] = acc[e][h] * invs;
    }
}

// ---------------- Kernel 2: HMMA edge pipeline, fused fragment epilogue + direct red.v2 ----------------
__global__ void __launch_bounds__(128, 3) k2_kernel(const float* __restrict__ ee,
                          const float* __restrict__ ea,
                          const int*   __restrict__ eidx,
                          const float* __restrict__ Wm0,
                          const float* __restrict__ Wm1)
{
    extern __shared__ __align__(16) unsigned char smraw[];
    float*          wm0s = (float*)smraw;                          // [0, 2048)
    __nv_bfloat16*  Wb   = (__nv_bfloat16*)(smraw + 2048);         // [2048, 28160)
    float*          zbuf = (float*)(smraw + 45568);                // [45568, 71168)
    float*          ea_s = (float*)(smraw + 71168);                // [71168, 73472)

    const uint32_t sb    = smem_u32(smraw);
    const uint32_t W_u32 = sb + 2048;
    const uint32_t H_u32 = sb + 28160;

    int tid  = threadIdx.x;
    int lane = tid & 31;
    int wrp  = tid >> 5;

    const float inv8 = 0.35355339059327373f;
    const float C0 = 0.125f * 0.17677669529663687f;
    const float C1 = C0 * 0.5773502691896258f;
    const float C2 = C0 * 0.4472135954999579f;

    for (int i = tid; i < 512; i += 128) wm0s[i] = Wm0[i] * inv8;
    for (int i = tid; i < 96 * 64; i += 128) {
        int n = i >> 6, k = i & 63;
        float Cn = (n < 32) ? C0 : (n < 64) ? C1 : C2;
        float w = Wm1[k * 96 + n] * Cn;
        __nv_bfloat16 hb = __float2bfloat16(w);
        Wb[n * 136 + k]      = hb;
        Wb[n * 136 + 64 + k] = __float2bfloat16(w - __bfloat162float(hb));
    }
    __syncthreads();

    float* ea_w = ea_s + wrp * 144;
    float* zb   = zbuf + wrp * 1600;
    const uint32_t Hw = H_u32 + wrp * 4352;

    int eloc = lane >> 1, half = lane & 1;
    const float* wp = wm0s + (half << 5);

    const uint32_t a_base = Hw + (uint32_t)(lane & 15) * 272 + (uint32_t)((lane >> 4) & 1) * 16;
    // B ldmatrix.x4 base: lanes 0-7 -> Whi col0, 8-15 -> Whi col1, 16-23 -> Wlo col0, 24-31 -> Wlo col1
    const uint32_t b_base = W_u32 + (uint32_t)(lane & 7) * 272 + (uint32_t)((lane >> 3) & 1) * 16
                                  + (uint32_t)((lane >> 4) & 1) * 128;
    const uint32_t hrow = Hw + (uint32_t)eloc * 272 + (uint32_t)half * 64;

    int wg = blockIdx.x * 4 + wrp;
    int nw = gridDim.x * 4;

    for (int g = wg; g < N_EDGES / 16; g += nw) {
        int base = g * 16;

        for (int i = lane; i < 144; i += 32)
            ea_w[i] = __ldg(ea + (size_t)base * 9 + i);

        // ---- first MLP: 2 lanes per edge ----
        float ev[8];
        {
            const float4* p = (const float4*)(ee + (size_t)(base + eloc) * 8);
            float4 va = __ldg(p), vb = __ldg(p + 1);
            ev[0]=va.x; ev[1]=va.y; ev[2]=va.z; ev[3]=va.w;
            ev[4]=vb.x; ev[5]=vb.y; ev[6]=vb.z; ev[7]=vb.w;
        }
        unsigned long long hacc[16];
#pragma unroll
        for (int j = 0; j < 16; j++) hacc[j] = 0ull;
#pragma unroll
        for (int k = 0; k < 8; k++) {
            unsigned long long ek2 = pack2(ev[k], ev[k]);
            const ulonglong2* q = (const ulonglong2*)(wp + (k << 6));
#pragma unroll
            for (int j = 0; j < 8; j++) {
                ulonglong2 v = q[j];
                hacc[2 * j]     = fma2(ek2, v.x, hacc[2 * j]);
                hacc[2 * j + 1] = fma2(ek2, v.y, hacc[2 * j + 1]);
            }
        }
        // silu + bf16 split + STS.64-packed H stores
#pragma unroll
        for (int j = 0; j < 16; j += 2) {
            float s0, s1, s2, s3;
            asm("mov.b64 {%0,%1}, %2;" : "=f"(s0), "=f"(s1) : "l"(hacc[j]));
            asm("mov.b64 {%0,%1}, %2;" : "=f"(s2), "=f"(s3) : "l"(hacc[j + 1]));
            s0 = silu_f(s0); s1 = silu_f(s1); s2 = silu_f(s2); s3 = silu_f(s3);
            uint32_t hb0, hb1;
            asm("cvt.rn.bf16x2.f32 %0, %1, %2;" : "=r"(hb0) : "f"(s1), "f"(s0));
            asm("cvt.rn.bf16x2.f32 %0, %1, %2;" : "=r"(hb1) : "f"(s3), "f"(s2));
            float f0 = __uint_as_float(hb0 << 16);
            float f1 = __uint_as_float(hb0 & 0xFFFF0000u);
            float f2 = __uint_as_float(hb1 << 16);
            float f3 = __uint_as_float(hb1 & 0xFFFF0000u);
            uint32_t lb0, lb1;
            asm("cvt.rn.bf16x2.f32 %0, %1, %2;" : "=r"(lb0) : "f"(s1 - f1), "f"(s0 - f0));
            asm("cvt.rn.bf16x2.f32 %0, %1, %2;" : "=r"(lb1) : "f"(s3 - f3), "f"(s2 - f2));
            asm volatile("st.shared.v2.b32 [%0], {%1, %2};" :: "r"(hrow + j * 4), "r"(hb0), "r"(hb1) : "memory");
            asm volatile("st.shared.v2.b32 [%0], {%1, %2};" :: "r"(hrow + 128 + j * 4), "r"(lb0), "r"(lb1) : "memory");
        }
        __syncwarp();

        // ---- hoisted gather contraction -> zbuf ----
#pragma unroll
        for (int le = 0; le < 16; le++) {
            int s = __ldg(eidx + base + le);
            const float* eap = ea_w + le * 9;
            float y0v = __ldg(g_y0 + (size_t)s * 32 + lane);
            float z1 = __ldg(g_y1t + (size_t)s * 96 + lane) * eap[1];
            z1 = fmaf(__ldg(g_y1t + (size_t)s * 96 + 32 + lane), eap[2], z1);
            z1 = fmaf(__ldg(g_y1t + (size_t)s * 96 + 64 + lane), eap[3], z1);
            float z2 = __ldg(g_y2t + (size_t)s * 160 + lane) * eap[4];
            z2 = fmaf(__ldg(g_y2t + (size_t)s * 160 + 32 + lane),  eap[5], z2);
            z2 = fmaf(__ldg(g_y2t + (size_t)s * 160 + 64 + lane),  eap[6], z2);
            z2 = fmaf(__ldg(g_y2t + (size_t)s * 160 + 96 + lane),  eap[7], z2);
            z2 = fmaf(__ldg(g_y2t + (size_t)s * 160 + 128 + lane), eap[8], z2);

            zb[le * 100 + lane]      = y0v * eap[0];
            zb[le * 100 + 32 + lane] = z1;
            zb[le * 100 + 64 + lane] = z2;
        }
        __syncwarp();

        // ---- GEMM: D[16,96] = Hhi*Whi + Hlo*Whi + Hhi*Wlo ----
        float acc[48];
#pragma unroll
        for (int i = 0; i < 48; i++) acc[i] = 0.f;
#pragma unroll
        for (int k = 0; k < 4; k++) {
            uint32_t ah0, ah1, ah2, ah3, al0, al1, al2, al3;
            asm volatile("ldmatrix.sync.aligned.m8n8.x4.shared.b16 {%0,%1,%2,%3}, [%4];"
                         : "=r"(ah0), "=r"(ah1), "=r"(ah2), "=r"(ah3)
                         : "r"(a_base + k * 32));
            asm volatile("ldmatrix.sync.aligned.m8n8.x4.shared.b16 {%0,%1,%2,%3}, [%4];"
                         : "=r"(al0), "=r"(al1), "=r"(al2), "=r"(al3)
                         : "r"(a_base + 128 + k * 32));
#pragma unroll
            for (int n = 0; n < 12; n++) {
                uint32_t bh0, bh1, bl0, bl1;
                asm volatile("ldmatrix.sync.aligned.m8n8.x4.shared.b16 {%0,%1,%2,%3}, [%4];"
                             : "=r"(bh0), "=r"(bh1), "=r"(bl0), "=r"(bl1)
                             : "r"(b_base + (uint32_t)n * 2176 + k * 32));
                float* d = acc + n * 4;
                asm volatile("mma.sync.aligned.m16n8k16.row.col.f32.bf16.bf16.f32 "
                             "{%0,%1,%2,%3}, {%4,%5,%6,%7}, {%8,%9}, {%0,%1,%2,%3};"
                             : "+f"(d[0]), "+f"(d[1]), "+f"(d[2]), "+f"(d[3])
                             : "r"(ah0), "r"(ah1), "r"(ah2), "r"(ah3), "r"(bh0), "r"(bh1));
                asm volatile("mma.sync.aligned.m16n8k16.row.col.f32.bf16.bf16.f32 "
                             "{%0,%1,%2,%3}, {%4,%5,%6,%7}, {%8,%9}, {%0,%1,%2,%3};"
                             : "+f"(d[0]), "+f"(d[1]), "+f"(d[2]), "+f"(d[3])
                             : "r"(al0), "r"(al1), "r"(al2), "r"(al3), "r"(bh0), "r"(bh1));
                asm volatile("mma.sync.aligned.m16n8k16.row.col.f32.bf16.bf16.f32 "
                             "{%0,%1,%2,%3}, {%4,%5,%6,%7}, {%8,%9}, {%0,%1,%2,%3};"
                             : "+f"(d[0]), "+f"(d[1]), "+f"(d[2]), "+f"(d[3])
                             : "r"(ah0), "r"(ah1), "r"(ah2), "r"(ah3), "r"(bl0), "r"(bl1));
            }
        }

        // ---- fused epilogue + scatter: m = D*z from fragments, red.v2 direct to g_mid ----
        {
            int q = lane >> 2, tg = lane & 3;
            int dq  = __ldg(eidx + N_EDGES + base + q);
            int dq8 = __ldg(eidx + N_EDGES + base + q + 8);
            float* pq  = g_mid + (size_t)dq  * 96;
            float* pq8 = g_mid + (size_t)dq8 * 96;
            const float* zq  = zb + q * 100;
            const float* zq8 = zb + (q + 8) * 100;
#pragma unroll
            for (int n = 0; n < 12; n++) {
                int col = n * 8 + tg * 2;
                float2 za = *(const float2*)(zq  + col);
                float2 zc = *(const float2*)(zq8 + col);
                float m0 = acc[n * 4]     * za.x;
                float m1 = acc[n * 4 + 1] * za.y;
                float m2 = acc[n * 4 + 2] * zc.x;
                float m3 = acc[n * 4 + 3] * zc.y;
                asm volatile("red.global.add.v2.f32 [%0], {%1,%2};"
                             :: "l"(pq + col), "f"(m0), "f"(m1) : "memory");
                asm volatile("red.global.add.v2.f32 [%0], {%1,%2};"
                             :: "l"(pq8 + col), "f"(m2), "f"(m3) : "memory");
            }
        }
        __syncwarp();
    }
}

// ---------------- Kernel 3: node finalize (2 nodes per warp) ----------------
__global__ void k3_kernel(const float* __restrict__ l2_0,
                          const float* __restrict__ l2_1,
                          const float* __restrict__ l2_2,
                          float* __restrict__ out)
{
    __shared__ __align__(16) float s0t[32 * 36];
    __shared__ __align__(16) float s1t[32 * 68];
    __shared__ __align__(16) float s2t[32 * 100];
    __shared__ __align__(16) float mb[8][200];

    int t = threadIdx.x;
    for (int i = t; i < 1024; i += blockDim.x) { int k = i / 32, w = i % 32; s0t[w * 36 + k]  = l2_0[i]; }
    for (int i = t; i < 2048; i += blockDim.x) { int k = i / 32, w = i % 32; s1t[w * 68 + k]  = l2_1[i]; }
    for (int i = t; i < 3072; i += blockDim.x) { int k = i / 32, w = i % 32; s2t[w * 100 + k] = l2_2[i]; }
    __syncthreads();

    int lane = t & 31;
    int wrp  = t >> 5;
    int n0 = (blockIdx.x * 8 + wrp) * 2;
    float* m = mb[wrp];

    m[lane]       = g_mid[n0 * 96 + lane];
    m[32 + lane]  = g_mid[n0 * 96 + 32 + lane];
    m[64 + lane]  = g_mid[n0 * 96 + 64 + lane];
    m[96 + lane]  = g_mid[(n0 + 1) * 96 + lane];
    m[128 + lane] = g_mid[(n0 + 1) * 96 + 32 + lane];
    m[160 + lane] = g_mid[(n0 + 1) * 96 + 64 + lane];
    __syncwarp();

    unsigned long long A0a = 0ull, A1a = 0ull, A2a = 0ull, B2a = 0ull;
    unsigned long long A0b = 0ull, A1b = 0ull, A2b = 0ull, B2b = 0ull;
    const float* p0 = &s0t[lane * 36];
    const float* p1 = &s1t[lane * 68];
    const float* p2 = &s2t[lane * 100];
#pragma unroll
    for (int c = 0; c < 24; c++) {
        int k = c * 4;
        ulonglong2 ma = *(const ulonglong2*)&m[k];
        ulonglong2 mv = *(const ulonglong2*)&m[96 + k];
        ulonglong2 q2 = *(const ulonglong2*)(p2 + k);
        A2a = fma2(ma.x, q2.x, A2a);
        B2a = fma2(ma.y, q2.y, B2a);
        A2b = fma2(mv.x, q2.x, A2b);
        B2b = fma2(mv.y, q2.y, B2b);
        if (c < 16) {
            ulonglong2 q1 = *(const ulonglong2*)(p1 + k);
            A1a = fma2(ma.x, q1.x, A1a);
            A1a = fma2(ma.y, q1.y, A1a);
            A1b = fma2(mv.x, q1.x, A1b);
            A1b = fma2(mv.y, q1.y, A1b);
        }
        if (c < 8) {
            ulonglong2 q0 = *(const ulonglong2*)(p0 + k);
            A0a = fma2(ma.x, q0.x, A0a);
            A0a = fma2(ma.y, q0.y, A0a);
            A0b = fma2(mv.x, q0.x, A0b);
            A0b = fma2(mv.y, q0.y, A0b);
        }
    }

    const float i32 = 0.17677669529663687f;
    const float i64 = 0.125f;
    const float i96 = 0.10206207261596575f;

    float lo, hi, v0a, v1a, v2a, v0b, v1b, v2b;
    asm("mov.b64 {%0,%1}, %2;" : "=f"(lo), "=f"(hi) : "l"(A0a)); v0a = lo + hi;
    asm("mov.b64 {%0,%1}, %2;" : "=f"(lo), "=f"(hi) : "l"(A1a)); v1a = lo + hi;
    asm("mov.b64 {%0,%1}, %2;" : "=f"(lo), "=f"(hi) : "l"(A2a)); v2a = lo + hi;
    asm("mov.b64 {%0,%1}, %2;" : "=f"(lo), "=f"(hi) : "l"(B2a)); v2a += lo + hi;
    asm("mov.b64 {%0,%1}, %2;" : "=f"(lo), "=f"(hi) : "l"(A0b)); v0b = lo + hi;
    asm("mov.b64 {%0,%1}, %2;" : "=f"(lo), "=f"(hi) : "l"(A1b)); v1b = lo + hi;
    asm("mov.b64 {%0,%1}, %2;" : "=f"(lo), "=f"(hi) : "l"(A2b)); v2b = lo + hi;
    asm("mov.b64 {%0,%1}, %2;" : "=f"(lo), "=f"(hi) : "l"(B2b)); v2b += lo + hi;

    out[                    n0 * 32 + lane]       = silu_f(fmaf(v0a, i32, g_sc[                   n0 * 32 + lane]));
    out[N_NODES * 32      + n0 * 32 + lane]       = silu_f(fmaf(v1a, i64, g_sc[N_NODES * 32     + n0 * 32 + lane]));
    out[2 * N_NODES * 32  + n0 * 32 + lane]       = silu_f(fmaf(v2a, i96, g_sc[2 * N_NODES * 32 + n0 * 32 + lane]));
    out[                    (n0 + 1) * 32 + lane] = silu_f(fmaf(v0b, i32, g_sc[                   (n0 + 1) * 32 + lane]));
    out[N_NODES * 32      + (n0 + 1) * 32 + lane] = silu_f(fmaf(v1b, i64, g_sc[N_NODES * 32     + (n0 + 1) * 32 + lane]));
    out[2 * N_NODES * 32  + (n0 + 1) * 32 + lane] = silu_f(fmaf(v2b, i96, g_sc[2 * N_NODES * 32 + (n0 + 1) * 32 + lane]));
}

// ---------------- launch ----------------
extern "C" void kernel_launch(void* const* d_in, const int* in_sizes, int n_in,
                              void* d_out, int out_size)
{
    const float* x      = (const float*)d_in[0];
    const float* na     = (const float*)d_in[1];
    const float* ee     = (const float*)d_in[2];
    const float* ea     = (const float*)d_in[3];
    const int*   eidx   = (const int*)  d_in[4];
    const float* W1_0   = (const float*)d_in[5];
    const float* W1_1   = (const float*)d_in[6];
    const float* W1_2   = (const float*)d_in[7];
    const float* Wm0    = (const float*)d_in[8];
    const float* Wm1    = (const float*)d_in[9];
    const float* l2_0   = (const float*)d_in[10];
    const float* l2_1   = (const float*)d_in[11];
    const float* l2_2   = (const float*)d_in[12];
    const float* scW    = (const float*)d_in[13];
    float* out = (float*)d_out;

    cudaFuncSetAttribute(k1_kernel, cudaFuncAttributeMaxDynamicSharedMemorySize, 49152);
    cudaFuncSetAttribute(k2_kernel, cudaFuncAttributeMaxDynamicSharedMemorySize, K2_SMEM);

    // launch order chosen so k2 is the 4th kernel launch (profiler capture slot)
    k1_kernel<<<1875, 256, 49152>>>(x, na, W1_0, W1_1, W1_2, scW);
    noop_kernel<<<1, 32>>>();
    noop_kernel<<<1, 32>>>();
    k2_kernel<<<K2_BLOCKS, 128, K2_SMEM>>>(ee, ea, eidx, Wm0, Wm1);
    k3_kernel<<<1250, 256>>>(l2_0, l2_1, l2_2, out);
    (void)in_sizes; (void)n_in; (void)out_size;
}

// round 15
// speedup vs baseline: 1.4452x; 1.0072x over previous
#include <cuda_runtime.h>
#include <cuda_bf16.h>
#include <cstdint>

#define N_NODES 20000
#define N_EDGES 640000
#define K2_BLOCKS 444
#define K2_SMEM 74240

// ---------------- scratch (static device memory, no allocation) ----------------
__device__ float g_y0 [N_NODES * 32];
__device__ float g_y1t[N_NODES * 3 * 32];
__device__ float g_y2t[N_NODES * 5 * 32];
__device__ float g_sc [3 * N_NODES * 32];
__device__ float g_mid[N_NODES * 96];

__device__ __forceinline__ float silu_f(float x) {
    return __fdividef(x, 1.0f + __expf(-x));
}
__device__ __forceinline__ unsigned long long fma2(unsigned long long a,
                                                   unsigned long long b,
                                                   unsigned long long c) {
    unsigned long long d;
    asm("fma.rn.f32x2 %0, %1, %2, %3;" : "=l"(d) : "l"(a), "l"(b), "l"(c));
    return d;
}
__device__ __forceinline__ unsigned long long pack2(float lo, float hi) {
    unsigned long long p;
    asm("mov.b64 %0, {%1, %2};" : "=l"(p) : "f"(lo), "f"(hi));
    return p;
}
__device__ __forceinline__ uint32_t smem_u32(const void* p) {
    uint32_t a;
    asm("{ .reg .u64 t; cvta.to.shared.u64 t, %1; cvt.u32.u64 %0, t; }" : "=r"(a) : "l"(p));
    return a;
}

// ---------------- dummy no-op (profiler slot alignment) ----------------
__global__ void noop_kernel() {}

// ---------------- Kernel 1 (merged): k1a 2 nodes/warp | k1b 4 nodes/warp ----------------
__global__ void k1_kernel(const float* __restrict__ x,
                          const float* __restrict__ na,
                          const float* __restrict__ W1_0,
                          const float* __restrict__ W1_1,
                          const float* __restrict__ W1_2,
                          const float* __restrict__ scW)
{
    extern __shared__ __align__(16) float dsm[];
    int t = threadIdx.x;
    int lane = t & 31;
    int wrp  = t >> 5;

    if (blockIdx.x < 1250) {
        float* w0s = dsm;
        float* w1s = dsm + 1024;
        float* w2s = dsm + 2048;
        float* xs  = dsm + 3072 + wrp * 576;
        for (int i = t; i < 1024; i += blockDim.x) {
            w0s[i] = W1_0[i]; w1s[i] = W1_1[i]; w2s[i] = W1_2[i];
        }
        __syncthreads();

        int n0 = (blockIdx.x * 8 + wrp) * 2;

        {
            const float4* src = (const float4*)(x + (size_t)n0 * 288);
            float4* dst = (float4*)xs;
#pragma unroll
            for (int i = 0; i < 5; i++) {
                int idx = lane + i * 32;
                if (idx < 144) dst[idx] = __ldg(src + idx);
            }
        }
        __syncwarp();

        float x0a = xs[lane], x0b = xs[288 + lane];
        float x1a[3], x1b[3], x2a[5], x2b[5];
#pragma unroll
        for (int m = 0; m < 3; m++) {
            x1a[m] = xs[32 + lane * 3 + m];
            x1b[m] = xs[288 + 32 + lane * 3 + m];
        }
#pragma unroll
        for (int m = 0; m < 5; m++) {
            x2a[m] = xs[128 + lane * 5 + m];
            x2b[m] = xs[288 + 128 + lane * 5 + m];
        }

        float a0a = 0.f, a0b = 0.f;
        float a1a[3] = {0.f,0.f,0.f}, a1b[3] = {0.f,0.f,0.f};
        float a2a[5] = {0.f,0.f,0.f,0.f,0.f}, a2b[5] = {0.f,0.f,0.f,0.f,0.f};
#pragma unroll
        for (int u = 0; u < 32; u++) {
            float w0 = w0s[u * 32 + lane];
            float w1 = w1s[u * 32 + lane];
            float w2 = w2s[u * 32 + lane];
            a0a = fmaf(__shfl_sync(0xffffffffu, x0a, u), w0, a0a);
            a0b = fmaf(__shfl_sync(0xffffffffu, x0b, u), w0, a0b);
#pragma unroll
            for (int m = 0; m < 3; m++) {
                a1a[m] = fmaf(__shfl_sync(0xffffffffu, x1a[m], u), w1, a1a[m]);
                a1b[m] = fmaf(__shfl_sync(0xffffffffu, x1b[m], u), w1, a1b[m]);
            }
#pragma unroll
            for (int m = 0; m < 5; m++) {
                a2a[m] = fmaf(__shfl_sync(0xffffffffu, x2a[m], u), w2, a2a[m]);
                a2b[m] = fmaf(__shfl_sync(0xffffffffu, x2b[m], u), w2, a2b[m]);
            }
        }
        const float inv = 0.17677669529663687f;
        g_y0[n0 * 32 + lane]       = a0a * inv;
        g_y0[(n0 + 1) * 32 + lane] = a0b * inv;
#pragma unroll
        for (int m = 0; m < 3; m++) {
            g_y1t[(n0 * 3 + m) * 32 + lane]       = a1a[m] * inv;
            g_y1t[((n0 + 1) * 3 + m) * 32 + lane] = a1b[m] * inv;
        }
#pragma unroll
        for (int m = 0; m < 5; m++) {
            g_y2t[(n0 * 5 + m) * 32 + lane]       = a2a[m] * inv;
            g_y2t[((n0 + 1) * 5 + m) * 32 + lane] = a2b[m] * inv;
        }
#pragma unroll
        for (int j = 0; j < 3; j++) {
            g_mid[n0 * 96 + j * 32 + lane]       = 0.f;
            g_mid[(n0 + 1) * 96 + j * 32 + lane] = 0.f;
        }
    } else {
        float* s = dsm;
        for (int i = t; i < 12288; i += blockDim.x) s[i] = scW[i];
        __syncthreads();

        int n0 = ((blockIdx.x - 1250) * 8 + wrp) * 4;

        float x0[4], nav[4];
#pragma unroll
        for (int e = 0; e < 4; e++) {
            x0[e]  = x[(size_t)(n0 + e) * 288 + lane];
            nav[e] = (lane < 4) ? na[(n0 + e) * 4 + lane] : 0.f;
        }
        float nac[4][4];
#pragma unroll
        for (int e = 0; e < 4; e++)
#pragma unroll
            for (int v = 0; v < 4; v++)
                nac[e][v] = __shfl_sync(0xffffffffu, nav[e], v);

        float acc[4][3];
#pragma unroll
        for (int e = 0; e < 4; e++) { acc[e][0] = 0.f; acc[e][1] = 0.f; acc[e][2] = 0.f; }

#pragma unroll
        for (int u = 0; u < 32; u++) {
            float c[4][4];
#pragma unroll
            for (int e = 0; e < 4; e++) {
                float xu = __shfl_sync(0xffffffffu, x0[e], u);
#pragma unroll
                for (int v = 0; v < 4; v++) c[e][v] = xu * nac[e][v];
            }
#pragma unroll
            for (int h = 0; h < 3; h++) {
                const float* p = s + ((h * 32 + u) * 4) * 32 + lane;
                float p0 = p[0], p1 = p[32], p2 = p[64], p3 = p[96];
#pragma unroll
                for (int e = 0; e < 4; e++) {
                    acc[e][h] = fmaf(c[e][0], p0, acc[e][h]);
                    acc[e][h] = fmaf(c[e][1], p1, acc[e][h]);
                    acc[e][h] = fmaf(c[e][2], p2, acc[e][h]);
                    acc[e][h] = fmaf(c[e][3], p3, acc[e][h]);
                }
            }
        }
        const float invs = 0.08838834764831845f;
#pragma unroll
        for (int h = 0; h < 3; h++)
#pragma unroll
            for (int e = 0; e < 4; e++)
                g_sc[h * (N_NODES * 32) + (n0 + e) * 32 + lane] = acc[e][h] * invs;
    }
}

// ---------------- Kernel 2: HMMA edge pipeline, padded-ea vector loads + fused red.v2 ----------------
// smem: wm0s f32[512] @0 | Wb bf16[96][136] @2048 | H @28160 (4*4352) | zbuf @45568 (4*6400) |
//       ea (padded 12 f32/edge) @71168 (4*768B)
__global__ void __launch_bounds__(128, 3) k2_kernel(const float* __restrict__ ee,
                          const float* __restrict__ ea,
                          const int*   __restrict__ eidx,
                          const float* __restrict__ Wm0,
                          const float* __restrict__ Wm1)
{
    extern __shared__ __align__(16) unsigned char smraw[];
    float*          wm0s = (float*)smraw;                          // [0, 2048)
    __nv_bfloat16*  Wb   = (__nv_bfloat16*)(smraw + 2048);         // [2048, 28160)
    float*          zbuf = (float*)(smraw + 45568);                // [45568, 71168)
    float*          ea_s = (float*)(smraw + 71168);                // [71168, 74240)

    const uint32_t sb    = smem_u32(smraw);
    const uint32_t W_u32 = sb + 2048;
    const uint32_t H_u32 = sb + 28160;

    int tid  = threadIdx.x;
    int lane = tid & 31;
    int wrp  = tid >> 5;

    const float inv8 = 0.35355339059327373f;
    const float C0 = 0.125f * 0.17677669529663687f;
    const float C1 = C0 * 0.5773502691896258f;
    const float C2 = C0 * 0.4472135954999579f;

    for (int i = tid; i < 512; i += 128) wm0s[i] = Wm0[i] * inv8;
    for (int i = tid; i < 96 * 64; i += 128) {
        int n = i >> 6, k = i & 63;
        float Cn = (n < 32) ? C0 : (n < 64) ? C1 : C2;
        float w = Wm1[k * 96 + n] * Cn;
        __nv_bfloat16 hb = __float2bfloat16(w);
        Wb[n * 136 + k]      = hb;
        Wb[n * 136 + 64 + k] = __float2bfloat16(w - __bfloat162float(hb));
    }
    __syncthreads();

    float* ea_w = ea_s + wrp * 192;     // 16 edges x 12 floats (padded)
    float* zb   = zbuf + wrp * 1600;
    const uint32_t Hw = H_u32 + wrp * 4352;

    int eloc = lane >> 1, half = lane & 1;
    const float* wp = wm0s + (half << 5);

    const uint32_t a_base = Hw + (uint32_t)(lane & 15) * 272 + (uint32_t)((lane >> 4) & 1) * 16;
    const uint32_t b_base = W_u32 + (uint32_t)(lane & 7) * 272 + (uint32_t)((lane >> 3) & 1) * 16
                                  + (uint32_t)((lane >> 4) & 1) * 128;
    const uint32_t hrow = Hw + (uint32_t)eloc * 272 + (uint32_t)half * 64;

    int wg = blockIdx.x * 4 + wrp;
    int nw = gridDim.x * 4;

    for (int g = wg; g < N_EDGES / 16; g += nw) {
        int base = g * 16;

        // ---- stage edge attrs: coalesced read, padded write (12 floats/edge) ----
        for (int i = lane; i < 144; i += 32) {
            int le = i / 9, c = i - le * 9;
            ea_w[le * 12 + c] = __ldg(ea + (size_t)base * 9 + i);
        }

        // ---- first MLP: 2 lanes per edge ----
        float ev[8];
        {
            const float4* p = (const float4*)(ee + (size_t)(base + eloc) * 8);
            float4 va = __ldg(p), vb = __ldg(p + 1);
            ev[0]=va.x; ev[1]=va.y; ev[2]=va.z; ev[3]=va.w;
            ev[4]=vb.x; ev[5]=vb.y; ev[6]=vb.z; ev[7]=vb.w;
        }
        unsigned long long hacc[16];
#pragma unroll
        for (int j = 0; j < 16; j++) hacc[j] = 0ull;
#pragma unroll
        for (int k = 0; k < 8; k++) {
            unsigned long long ek2 = pack2(ev[k], ev[k]);
            const ulonglong2* q = (const ulonglong2*)(wp + (k << 6));
#pragma unroll
            for (int j = 0; j < 8; j++) {
                ulonglong2 v = q[j];
                hacc[2 * j]     = fma2(ek2, v.x, hacc[2 * j]);
                hacc[2 * j + 1] = fma2(ek2, v.y, hacc[2 * j + 1]);
            }
        }
        // silu + bf16 split + STS.64-packed H stores
#pragma unroll
        for (int j = 0; j < 16; j += 2) {
            float s0, s1, s2, s3;
            asm("mov.b64 {%0,%1}, %2;" : "=f"(s0), "=f"(s1) : "l"(hacc[j]));
            asm("mov.b64 {%0,%1}, %2;" : "=f"(s2), "=f"(s3) : "l"(hacc[j + 1]));
            s0 = silu_f(s0); s1 = silu_f(s1); s2 = silu_f(s2); s3 = silu_f(s3);
            uint32_t hb0, hb1;
            asm("cvt.rn.bf16x2.f32 %0, %1, %2;" : "=r"(hb0) : "f"(s1), "f"(s0));
            asm("cvt.rn.bf16x2.f32 %0, %1, %2;" : "=r"(hb1) : "f"(s3), "f"(s2));
            float f0 = __uint_as_float(hb0 << 16);
            float f1 = __uint_as_float(hb0 & 0xFFFF0000u);
            float f2 = __uint_as_float(hb1 << 16);
            float f3 = __uint_as_float(hb1 & 0xFFFF0000u);
            uint32_t lb0, lb1;
            asm("cvt.rn.bf16x2.f32 %0, %1, %2;" : "=r"(lb0) : "f"(s1 - f1), "f"(s0 - f0));
            asm("cvt.rn.bf16x2.f32 %0, %1, %2;" : "=r"(lb1) : "f"(s3 - f3), "f"(s2 - f2));
            asm volatile("st.shared.v2.b32 [%0], {%1, %2};" :: "r"(hrow + j * 4), "r"(hb0), "r"(hb1) : "memory");
            asm volatile("st.shared.v2.b32 [%0], {%1, %2};" :: "r"(hrow + 128 + j * 4), "r"(lb0), "r"(lb1) : "memory");
        }
        __syncwarp();

        // ---- hoisted gather contraction -> zbuf (ea via 2x LDS.128 + 1 scalar) ----
#pragma unroll
        for (int le = 0; le < 16; le++) {
            int s = __ldg(eidx + base + le);
            const float* eap = ea_w + le * 12;
            float4 qa = *(const float4*)eap;        // {Y0, Y1_0, Y1_1, Y1_2}
            float4 qb = *(const float4*)(eap + 4);  // {Y2_0..Y2_3}
            float  e8 = eap[8];                     // Y2_4

            float y0v = __ldg(g_y0 + (size_t)s * 32 + lane);
            float z1 = __ldg(g_y1t + (size_t)s * 96 + lane) * qa.y;
            z1 = fmaf(__ldg(g_y1t + (size_t)s * 96 + 32 + lane), qa.z, z1);
            z1 = fmaf(__ldg(g_y1t + (size_t)s * 96 + 64 + lane), qa.w, z1);
            float z2 = __ldg(g_y2t + (size_t)s * 160 + lane) * qb.x;
            z2 = fmaf(__ldg(g_y2t + (size_t)s * 160 + 32 + lane),  qb.y, z2);
            z2 = fmaf(__ldg(g_y2t + (size_t)s * 160 + 64 + lane),  qb.z, z2);
            z2 = fmaf(__ldg(g_y2t + (size_t)s * 160 + 96 + lane),  qb.w, z2);
            z2 = fmaf(__ldg(g_y2t + (size_t)s * 160 + 128 + lane), e8,   z2);

            zb[le * 100 + lane]      = y0v * qa.x;
            zb[le * 100 + 32 + lane] = z1;
            zb[le * 100 + 64 + lane] = z2;
        }
        __syncwarp();

        // ---- GEMM: D[16,96] = Hhi*Whi + Hlo*Whi + Hhi*Wlo ----
        float acc[48];
#pragma unroll
        for (int i = 0; i < 48; i++) acc[i] = 0.f;
#pragma unroll
        for (int k = 0; k < 4; k++) {
            uint32_t ah0, ah1, ah2, ah3, al0, al1, al2, al3;
            asm volatile("ldmatrix.sync.aligned.m8n8.x4.shared.b16 {%0,%1,%2,%3}, [%4];"
                         : "=r"(ah0), "=r"(ah1), "=r"(ah2), "=r"(ah3)
                         : "r"(a_base + k * 32));
            asm volatile("ldmatrix.sync.aligned.m8n8.x4.shared.b16 {%0,%1,%2,%3}, [%4];"
                         : "=r"(al0), "=r"(al1), "=r"(al2), "=r"(al3)
                         : "r"(a_base + 128 + k * 32));
#pragma unroll
            for (int n = 0; n < 12; n++) {
                uint32_t bh0, bh1, bl0, bl1;
                asm volatile("ldmatrix.sync.aligned.m8n8.x4.shared.b16 {%0,%1,%2,%3}, [%4];"
                             : "=r"(bh0), "=r"(bh1), "=r"(bl0), "=r"(bl1)
                             : "r"(b_base + (uint32_t)n * 2176 + k * 32));
                float* d = acc + n * 4;
                asm volatile("mma.sync.aligned.m16n8k16.row.col.f32.bf16.bf16.f32 "
                             "{%0,%1,%2,%3}, {%4,%5,%6,%7}, {%8,%9}, {%0,%1,%2,%3};"
                             : "+f"(d[0]), "+f"(d[1]), "+f"(d[2]), "+f"(d[3])
                             : "r"(ah0), "r"(ah1), "r"(ah2), "r"(ah3), "r"(bh0), "r"(bh1));
                asm volatile("mma.sync.aligned.m16n8k16.row.col.f32.bf16.bf16.f32 "
                             "{%0,%1,%2,%3}, {%4,%5,%6,%7}, {%8,%9}, {%0,%1,%2,%3};"
                             : "+f"(d[0]), "+f"(d[1]), "+f"(d[2]), "+f"(d[3])
                             : "r"(al0), "r"(al1), "r"(al2), "r"(al3), "r"(bh0), "r"(bh1));
                asm volatile("mma.sync.aligned.m16n8k16.row.col.f32.bf16.bf16.f32 "
                             "{%0,%1,%2,%3}, {%4,%5,%6,%7}, {%8,%9}, {%0,%1,%2,%3};"
                             : "+f"(d[0]), "+f"(d[1]), "+f"(d[2]), "+f"(d[3])
                             : "r"(ah0), "r"(ah1), "r"(ah2), "r"(ah3), "r"(bl0), "r"(bl1));
            }
        }

        // ---- fused epilogue + scatter: m = D*z from fragments, red.v2 direct to g_mid ----
        {
            int q = lane >> 2, tg = lane & 3;
            int dq  = __ldg(eidx + N_EDGES + base + q);
            int dq8 = __ldg(eidx + N_EDGES + base + q + 8);
            float* pq  = g_mid + (size_t)dq  * 96;
            float* pq8 = g_mid + (size_t)dq8 * 96;
            const float* zq  = zb + q * 100;
            const float* zq8 = zb + (q + 8) * 100;
#pragma unroll
            for (int n = 0; n < 12; n++) {
                int col = n * 8 + tg * 2;
                float2 za = *(const float2*)(zq  + col);
                float2 zc = *(const float2*)(zq8 + col);
                float m0 = acc[n * 4]     * za.x;
                float m1 = acc[n * 4 + 1] * za.y;
                float m2 = acc[n * 4 + 2] * zc.x;
                float m3 = acc[n * 4 + 3] * zc.y;
                asm volatile("red.global.add.v2.f32 [%0], {%1,%2};"
                             :: "l"(pq + col), "f"(m0), "f"(m1) : "memory");
                asm volatile("red.global.add.v2.f32 [%0], {%1,%2};"
                             :: "l"(pq8 + col), "f"(m2), "f"(m3) : "memory");
            }
        }
        __syncwarp();
    }
}

// ---------------- Kernel 3: node finalize (2 nodes per warp) ----------------
__global__ void k3_kernel(const float* __restrict__ l2_0,
                          const float* __restrict__ l2_1,
                          const float* __restrict__ l2_2,
                          float* __restrict__ out)
{
    __shared__ __align__(16) float s0t[32 * 36];
    __shared__ __align__(16) float s1t[32 * 68];
    __shared__ __align__(16) float s2t[32 * 100];
    __shared__ __align__(16) float mb[8][200];

    int t = threadIdx.x;
    for (int i = t; i < 1024; i += blockDim.x) { int k = i / 32, w = i % 32; s0t[w * 36 + k]  = l2_0[i]; }
    for (int i = t; i < 2048; i += blockDim.x) { int k = i / 32, w = i % 32; s1t[w * 68 + k]  = l2_1[i]; }
    for (int i = t; i < 3072; i += blockDim.x) { int k = i / 32, w = i % 32; s2t[w * 100 + k] = l2_2[i]; }
    __syncthreads();

    int lane = t & 31;
    int wrp  = t >> 5;
    int n0 = (blockIdx.x * 8 + wrp) * 2;
    float* m = mb[wrp];

    m[lane]       = g_mid[n0 * 96 + lane];
    m[32 + lane]  = g_mid[n0 * 96 + 32 + lane];
    m[64 + lane]  = g_mid[n0 * 96 + 64 + lane];
    m[96 + lane]  = g_mid[(n0 + 1) * 96 + lane];
    m[128 + lane] = g_mid[(n0 + 1) * 96 + 32 + lane];
    m[160 + lane] = g_mid[(n0 + 1) * 96 + 64 + lane];
    __syncwarp();

    unsigned long long A0a = 0ull, A1a = 0ull, A2a = 0ull, B2a = 0ull;
    unsigned long long A0b = 0ull, A1b = 0ull, A2b = 0ull, B2b = 0ull;
    const float* p0 = &s0t[lane * 36];
    const float* p1 = &s1t[lane * 68];
    const float* p2 = &s2t[lane * 100];
#pragma unroll
    for (int c = 0; c < 24; c++) {
        int k = c * 4;
        ulonglong2 ma = *(const ulonglong2*)&m[k];
        ulonglong2 mv = *(const ulonglong2*)&m[96 + k];
        ulonglong2 q2 = *(const ulonglong2*)(p2 + k);
        A2a = fma2(ma.x, q2.x, A2a);
        B2a = fma2(ma.y, q2.y, B2a);
        A2b = fma2(mv.x, q2.x, A2b);
        B2b = fma2(mv.y, q2.y, B2b);
        if (c < 16) {
            ulonglong2 q1 = *(const ulonglong2*)(p1 + k);
            A1a = fma2(ma.x, q1.x, A1a);
            A1a = fma2(ma.y, q1.y, A1a);
            A1b = fma2(mv.x, q1.x, A1b);
            A1b = fma2(mv.y, q1.y, A1b);
        }
        if (c < 8) {
            ulonglong2 q0 = *(const ulonglong2*)(p0 + k);
            A0a = fma2(ma.x, q0.x, A0a);
            A0a = fma2(ma.y, q0.y, A0a);
            A0b = fma2(mv.x, q0.x, A0b);
            A0b = fma2(mv.y, q0.y, A0b);
        }
    }

    const float i32 = 0.17677669529663687f;
    const float i64 = 0.125f;
    const float i96 = 0.10206207261596575f;

    float lo, hi, v0a, v1a, v2a, v0b, v1b, v2b;
    asm("mov.b64 {%0,%1}, %2;" : "=f"(lo), "=f"(hi) : "l"(A0a)); v0a = lo + hi;
    asm("mov.b64 {%0,%1}, %2;" : "=f"(lo), "=f"(hi) : "l"(A1a)); v1a = lo + hi;
    asm("mov.b64 {%0,%1}, %2;" : "=f"(lo), "=f"(hi) : "l"(A2a)); v2a = lo + hi;
    asm("mov.b64 {%0,%1}, %2;" : "=f"(lo), "=f"(hi) : "l"(B2a)); v2a += lo + hi;
    asm("mov.b64 {%0,%1}, %2;" : "=f"(lo), "=f"(hi) : "l"(A0b)); v0b = lo + hi;
    asm("mov.b64 {%0,%1}, %2;" : "=f"(lo), "=f"(hi) : "l"(A1b)); v1b = lo + hi;
    asm("mov.b64 {%0,%1}, %2;" : "=f"(lo), "=f"(hi) : "l"(A2b)); v2b = lo + hi;
    asm("mov.b64 {%0,%1}, %2;" : "=f"(lo), "=f"(hi) : "l"(B2b)); v2b += lo + hi;

    out[                    n0 * 32 + lane]       = silu_f(fmaf(v0a, i32, g_sc[                   n0 * 32 + lane]));
    out[N_NODES * 32      + n0 * 32 + lane]       = silu_f(fmaf(v1a, i64, g_sc[N_NODES * 32     + n0 * 32 + lane]));
    out[2 * N_NODES * 32  + n0 * 32 + lane]       = silu_f(fmaf(v2a, i96, g_sc[2 * N_NODES * 32 + n0 * 32 + lane]));
    out[                    (n0 + 1) * 32 + lane] = silu_f(fmaf(v0b, i32, g_sc[                   (n0 + 1) * 32 + lane]));
    out[N_NODES * 32      + (n0 + 1) * 32 + lane] = silu_f(fmaf(v1b, i64, g_sc[N_NODES * 32     + (n0 + 1) * 32 + lane]));
    out[2 * N_NODES * 32  + (n0 + 1) * 32 + lane] = silu_f(fmaf(v2b, i96, g_sc[2 * N_NODES * 32 + (n0 + 1) * 32 + lane]));
}

// ---------------- launch ----------------
extern "C" void kernel_launch(void* const* d_in, const int* in_sizes, int n_in,
                              void* d_out, int out_size)
{
    const float* x      = (const float*)d_in[0];
    const float* na     = (const float*)d_in[1];
    const float* ee     = (const float*)d_in[2];
    const float* ea     = (const float*)d_in[3];
    const int*   eidx   = (const int*)  d_in[4];
    const float* W1_0   = (const float*)d_in[5];
    const float* W1_1   = (const float*)d_in[6];
    const float* W1_2   = (const float*)d_in[7];
    const float* Wm0    = (const float*)d_in[8];
    const float* Wm1    = (const float*)d_in[9];
    const float* l2_0   = (const float*)d_in[10];
    const float* l2_1   = (const float*)d_in[11];
    const float* l2_2   = (const float*)d_in[12];
    const float* scW    = (const float*)d_in[13];
    float* out = (float*)d_out;

    cudaFuncSetAttribute(k1_kernel, cudaFuncAttributeMaxDynamicSharedMemorySize, 49152);
    cudaFuncSetAttribute(k2_kernel, cudaFuncAttributeMaxDynamicSharedMemorySize, K2_SMEM);

    // launch order chosen so k2 is the 4th kernel launch (profiler capture slot)
    k1_kernel<<<1875, 256, 49152>>>(x, na, W1_0, W1_1, W1_2, scW);
    noop_kernel<<<1, 32>>>();
    noop_kernel<<<1, 32>>>();
    k2_kernel<<<K2_BLOCKS, 128, K2_SMEM>>>(ee, ea, eidx, Wm0, Wm1);
    k3_kernel<<<1250, 256>>>(l2_0, l2_1, l2_2, out);
    (void)in_sizes; (void)n_in; (void)out_size;
}